// round 6
// baseline (speedup 1.0000x reference)
#include <cuda_runtime.h>
#include <cstdint>

#define NIMG   4096
#define TSTEPS 128
#define BATCH  32
#define HID    128

// Scratch (device globals; no allocation allowed)
__device__ float g_z1[(size_t)NIMG * 4 * 400 * 8];    // conv1 out [n][g=oc/8][pix400][oc%8]
__device__ float g_z2[(size_t)NIMG * 4 * 81 * 16];    // conv2 out [n][cc=oc/16][pix81][oc%16]
__device__ float g_z3[(size_t)NIMG * 3136];           // conv3 out, NCHW flatten
__device__ float g_hidden[(size_t)NIMG * 512];        // FC out
__device__ float g_gates[(size_t)NIMG * 512];         // x-proj of gates (+both biases)
__device__ float g_hs[(size_t)NIMG * HID];            // per-step hidden outputs
__device__ float g_whhT[HID * 512];                   // W_hh transposed: [k][row j]

// ---------------------------------------------------------------------------
// conv1: 1x84x84 -> 32x20x20, k=8, s=4. One block per image. (round-1 proven)
// ---------------------------------------------------------------------------
__global__ __launch_bounds__(512) void conv1_kernel(const float* __restrict__ x,
                                                    const float* __restrict__ W1,
                                                    const float* __restrict__ b1) {
    __shared__ float img[84 * 84];
    __shared__ float ws[64 * 32];   // [k][oc]
    __shared__ float bs[32];
    const int n = blockIdx.x;
    const int tid = threadIdx.x;
    const float* xin = x + (size_t)n * 7056;
    for (int i = tid; i < 7056; i += 512) img[i] = xin[i] * (1.0f / 255.0f);
    for (int i = tid; i < 2048; i += 512) {
        int k = i >> 5, oc = i & 31;
        ws[i] = W1[oc * 64 + k];
    }
    if (tid < 32) bs[tid] = b1[tid];
    __syncthreads();

    if (tid < 400) {
        const int oy = tid / 20, ox = tid % 20;
        const int iy = oy * 4, ix = ox * 4;
        float acc[32];
#pragma unroll
        for (int o = 0; o < 32; o++) acc[o] = 0.f;
#pragma unroll
        for (int ky = 0; ky < 8; ky++) {
            const float* ip = &img[(iy + ky) * 84 + ix];
            float v[8];
#pragma unroll
            for (int kx = 0; kx < 8; kx++) v[kx] = ip[kx];
#pragma unroll
            for (int kx = 0; kx < 8; kx++) {
                const float* wp = &ws[(ky * 8 + kx) * 32];
                float vv = v[kx];
#pragma unroll
                for (int o = 0; o < 32; o++) acc[o] += vv * wp[o];
            }
        }
        float* zp = g_z1 + (size_t)n * 12800;
#pragma unroll
        for (int o = 0; o < 32; o++) {
            float r = fmaxf(acc[o] + bs[o], 0.f);
            int g = o >> 3, l = o & 7;
            zp[(g * 400 + tid) * 8 + l] = r;
        }
    }
}

// ---------------------------------------------------------------------------
// conv2: 32x20x20 -> 64x9x9, k=4, s=2. One image per 224-thread block.
// 27 pixel-triples x 8 oc-groups = 216 active; 24 accums; R = 8.7 FFMA/LDS128.
// ---------------------------------------------------------------------------
__global__ __launch_bounds__(224, 3) void conv2_kernel(const float* __restrict__ W2,
                                                       const float* __restrict__ b2) {
    __shared__ float in_s[400 * 8];     // [pix][ic8]      12.5KB
    __shared__ float w_s[64 * 16 * 8];  // [oc][k16][ic8]  32KB
    const int n = blockIdx.x;
    const int tid = threadIdx.x;
    const int ocg  = tid & 7;
    const int trip = tid >> 3;          // 0..27
    const bool active = (trip < 27);

    int py[3], px[3];
#pragma unroll
    for (int i = 0; i < 3; i++) {
        int p = trip * 3 + i;
        if (p > 80) p = 80;
        py[i] = p / 9; px[i] = p % 9;
    }

    float acc[3][8];
#pragma unroll
    for (int i = 0; i < 3; i++)
#pragma unroll
        for (int o = 0; o < 8; o++) acc[i][o] = 0.f;

    for (int c = 0; c < 4; c++) {
        __syncthreads();
        const float* zin = g_z1 + ((size_t)n * 4 + c) * 3200;
        for (int i = tid; i < 3200; i += 224) in_s[i] = zin[i];
        for (int i = tid; i < 8192; i += 224) {
            int oc = i >> 7, rr = i & 127, k = rr >> 3, icl = rr & 7;
            w_s[i] = W2[oc * 512 + (c * 8 + icl) * 16 + k];
        }
        __syncthreads();
        if (active) {
#pragma unroll
            for (int k = 0; k < 16; k++) {
                const int ky = k >> 2, kx = k & 3;
                float4 a[3][2];
#pragma unroll
                for (int i = 0; i < 3; i++) {
                    const int ib = ((py[i] * 2 + ky) * 20 + px[i] * 2 + kx) * 8;
                    a[i][0] = *(const float4*)&in_s[ib];
                    a[i][1] = *(const float4*)&in_s[ib + 4];
                }
#pragma unroll
                for (int o = 0; o < 8; o++) {
                    const float4* wp = (const float4*)&w_s[((ocg * 8 + o) * 16 + k) * 8];
                    const float4 w0 = wp[0], w1 = wp[1];
#pragma unroll
                    for (int i = 0; i < 3; i++) {
                        acc[i][o] += a[i][0].x * w0.x + a[i][0].y * w0.y +
                                     a[i][0].z * w0.z + a[i][0].w * w0.w +
                                     a[i][1].x * w1.x + a[i][1].y * w1.y +
                                     a[i][1].z * w1.z + a[i][1].w * w1.w;
                    }
                }
            }
        }
    }
    if (active) {
#pragma unroll
        for (int i = 0; i < 3; i++) {
            const int p = trip * 3 + i;
#pragma unroll
            for (int o = 0; o < 8; o++) {
                const int oc = ocg * 8 + o;
                const float v = fmaxf(acc[i][o] + b2[oc], 0.f);
                g_z2[(((size_t)n * 4 + (oc >> 4)) * 81 + p) * 16 + (oc & 15)] = v;
            }
        }
    }
}

// ---------------------------------------------------------------------------
// conv3: 64x9x9 -> 64x7x7, k=3, s=1. One image per 128-thread block.
// 7 rows x 16 ocg(4) = 112 active; 28 accums; R = 10.2 FFMA/LDS128.
// ---------------------------------------------------------------------------
__global__ __launch_bounds__(128, 4) void conv3_kernel(const float* __restrict__ W3,
                                                       const float* __restrict__ b3) {
    __shared__ float in_s[81 * 16];     // [pix][ic16]    5.2KB
    __shared__ float w_s[64 * 9 * 16];  // [oc][k9][ic16] 36.9KB
    const int n = blockIdx.x;
    const int tid = threadIdx.x;
    const int ty  = tid / 16;    // output row 0..6 (tid<112)
    const int og  = tid % 16;    // oc group (4 oc each)
    const bool active = (tid < 112);

    float acc[7][4];
#pragma unroll
    for (int i = 0; i < 7; i++)
#pragma unroll
        for (int o = 0; o < 4; o++) acc[i][o] = 0.f;

    for (int cc = 0; cc < 4; cc++) {
        __syncthreads();
        const float* zin = g_z2 + ((size_t)n * 4 + cc) * 1296;
        for (int i = tid; i < 1296; i += 128) in_s[i] = zin[i];
        for (int i = tid; i < 9216; i += 128) {
            const int oc = i / 144, r2 = i % 144, k = r2 >> 4, icl = r2 & 15;
            w_s[i] = W3[oc * 576 + (cc * 16 + icl) * 9 + k];
        }
        __syncthreads();
        if (active) {
#pragma unroll
            for (int k = 0; k < 9; k++) {
                const int ky = k / 3, kx = k % 3;
#pragma unroll
                for (int icv = 0; icv < 4; icv++) {
                    float4 av[7];
#pragma unroll
                    for (int ox = 0; ox < 7; ox++)
                        av[ox] = *(const float4*)&in_s[((ty + ky) * 9 + kx + ox) * 16 + icv * 4];
#pragma unroll
                    for (int o = 0; o < 4; o++) {
                        const float4 w = *(const float4*)&w_s[((og * 4 + o) * 9 + k) * 16 + icv * 4];
#pragma unroll
                        for (int ox = 0; ox < 7; ox++) {
                            acc[ox][o] += av[ox].x * w.x + av[ox].y * w.y +
                                          av[ox].z * w.z + av[ox].w * w.w;
                        }
                    }
                }
            }
        }
    }
    if (active) {
#pragma unroll
        for (int o = 0; o < 4; o++) {
            const int oc = og * 4 + o;
            const float bb = b3[oc];
            float* zp = &g_z3[(size_t)n * 3136 + oc * 49 + ty * 7];
#pragma unroll
            for (int ox = 0; ox < 7; ox++)
                zp[ox] = fmaxf(acc[ox][o] + bb, 0.f);
        }
    }
}

// ---------------------------------------------------------------------------
// GEMM: C[M,N] = A[M,K] * B[N,K]^T + bias(+bias2), optional relu.
// BM=BN=64, BK=16, 256 threads, 4x4 microtile (round-1 proven).
// ---------------------------------------------------------------------------
__device__ __forceinline__ void gemm_body(const float* __restrict__ A,
                                          const float* __restrict__ B,
                                          float* __restrict__ C, int K,
                                          const float* __restrict__ bias1,
                                          const float* __restrict__ bias2,
                                          bool relu) {
    __shared__ float As[16 * 68];
    __shared__ float Bs[16 * 68];
    const int tid = threadIdx.x;
    const int m0 = blockIdx.y * 64, n0 = blockIdx.x * 64;
    const int ar = tid >> 2, ac = (tid & 3) << 2;
    const int tx = tid & 15, ty = tid >> 4;
    const int N = 512;

    float acc[4][4];
#pragma unroll
    for (int i = 0; i < 4; i++)
#pragma unroll
        for (int j = 0; j < 4; j++) acc[i][j] = 0.f;

    const float* Ap = A + (size_t)(m0 + ar) * K + ac;
    const float* Bp = B + (size_t)(n0 + ar) * K + ac;

    for (int k0 = 0; k0 < K; k0 += 16) {
        const float4 av = *(const float4*)(Ap + k0);
        const float4 bv = *(const float4*)(Bp + k0);
        As[(ac + 0) * 68 + ar] = av.x;
        As[(ac + 1) * 68 + ar] = av.y;
        As[(ac + 2) * 68 + ar] = av.z;
        As[(ac + 3) * 68 + ar] = av.w;
        Bs[(ac + 0) * 68 + ar] = bv.x;
        Bs[(ac + 1) * 68 + ar] = bv.y;
        Bs[(ac + 2) * 68 + ar] = bv.z;
        Bs[(ac + 3) * 68 + ar] = bv.w;
        __syncthreads();
#pragma unroll
        for (int kk = 0; kk < 16; kk++) {
            const float4 a = *(const float4*)&As[kk * 68 + (ty << 2)];
            const float4 b = *(const float4*)&Bs[kk * 68 + (tx << 2)];
            acc[0][0] += a.x * b.x; acc[0][1] += a.x * b.y;
            acc[0][2] += a.x * b.z; acc[0][3] += a.x * b.w;
            acc[1][0] += a.y * b.x; acc[1][1] += a.y * b.y;
            acc[1][2] += a.y * b.z; acc[1][3] += a.y * b.w;
            acc[2][0] += a.z * b.x; acc[2][1] += a.z * b.y;
            acc[2][2] += a.z * b.z; acc[2][3] += a.z * b.w;
            acc[3][0] += a.w * b.x; acc[3][1] += a.w * b.y;
            acc[3][2] += a.w * b.z; acc[3][3] += a.w * b.w;
        }
        __syncthreads();
    }

    float bb[4];
#pragma unroll
    for (int j = 0; j < 4; j++) {
        int nn = n0 + (tx << 2) + j;
        bb[j] = bias1[nn] + (bias2 ? bias2[nn] : 0.f);
    }
#pragma unroll
    for (int i = 0; i < 4; i++) {
        float4 o;
        float v0 = acc[i][0] + bb[0], v1 = acc[i][1] + bb[1];
        float v2 = acc[i][2] + bb[2], v3 = acc[i][3] + bb[3];
        if (relu) {
            v0 = fmaxf(v0, 0.f); v1 = fmaxf(v1, 0.f);
            v2 = fmaxf(v2, 0.f); v3 = fmaxf(v3, 0.f);
        }
        o.x = v0; o.y = v1; o.z = v2; o.w = v3;
        *(float4*)&C[(size_t)(m0 + (ty << 2) + i) * N + n0 + (tx << 2)] = o;
    }
}

__global__ __launch_bounds__(256) void fc_gemm_kernel(const float* __restrict__ Wfc,
                                                      const float* __restrict__ bfc) {
    gemm_body(g_z3, Wfc, g_hidden, 3136, bfc, nullptr, true);
}
__global__ __launch_bounds__(256) void gates_gemm_kernel(const float* __restrict__ W_ih,
                                                         const float* __restrict__ b_ih,
                                                         const float* __restrict__ b_hh) {
    gemm_body(g_hidden, W_ih, g_gates, 512, b_ih, b_hh, false);
}

// ---------------------------------------------------------------------------
// W_hh transpose prep: g_whhT[k*512 + j] = W_hh[j*128 + k]
// ---------------------------------------------------------------------------
__global__ __launch_bounds__(512) void whh_transpose_kernel(const float* __restrict__ W_hh) {
    const int id = blockIdx.x * 512 + threadIdx.x;   // 0..65535
    const int k = id >> 9, j = id & 511;
    g_whhT[k * 512 + j] = W_hh[j * 128 + k];
}

// ---------------------------------------------------------------------------
// LSTM: one block per batch element, 512 threads, no grid barrier.
// (round-4/5 proven coalesced version)
// ---------------------------------------------------------------------------
__device__ __forceinline__ float sigmoidf_(float v) {
    return 1.0f / (1.0f + __expf(-v));
}

__global__ __launch_bounds__(512) void lstm_kernel(const float* __restrict__ done,
                                                   const float* __restrict__ h0,
                                                   const float* __restrict__ c0,
                                                   float* __restrict__ out) {
    __shared__ float hm[HID];          // masked previous h
    __shared__ float cs[HID];
    __shared__ float hs[HID];
    __shared__ float part[4 * 512];    // [ks][gate row]
    const int b = blockIdx.x;
    const int tid = threadIdx.x;
    const int j4 = tid & 127;
    const int ks = tid >> 7;

    if (tid < HID) {
        hs[tid] = h0[b * HID + tid];
        cs[tid] = c0[b * HID + tid];
    }
    __syncthreads();

    for (int t = 0; t < TSTEPS; t++) {
        const float mask = 1.0f - done[t * BATCH + b];
        if (tid < HID) hm[tid] = hs[tid] * mask;
        __syncthreads();

        float a0 = 0.f, a1 = 0.f, a2 = 0.f, a3 = 0.f;
        const float4* __restrict__ wt = (const float4*)&g_whhT[(ks * 32) * 512] + j4;
        const float* __restrict__ hk = &hm[ks * 32];
#pragma unroll
        for (int kk = 0; kk < 32; kk++) {
            const float4 w = wt[kk * 128];
            const float h = hk[kk];
            a0 += w.x * h; a1 += w.y * h; a2 += w.z * h; a3 += w.w * h;
        }
        float4 pv = {a0, a1, a2, a3};
        *(float4*)&part[ks * 512 + j4 * 4] = pv;
        __syncthreads();

        // combine partials + x-projection; compute gate j = tid
        const float gx = g_gates[(size_t)(t * BATCH + b) * 512 + tid];
        const float gsum = part[tid] + part[512 + tid] + part[1024 + tid] +
                           part[1536 + tid] + gx;
        part[tid] = gsum;   // reuse as gate buffer (each thread rewrites own slot)
        __syncthreads();

        if (tid < HID) {
            const float gi = part[tid];
            const float gf = part[tid + 128];
            const float gc = part[tid + 256];
            const float go = part[tid + 384];
            float c = cs[tid] * mask;
            c = sigmoidf_(gf) * c + sigmoidf_(gi) * tanhf(gc);
            const float h = sigmoidf_(go) * tanhf(c);
            cs[tid] = c;
            hs[tid] = h;
            g_hs[(size_t)(t * BATCH + b) * HID + tid] = h;
            if (t == TSTEPS - 1) {
                out[28672 + b * HID + tid] = h;
                out[32768 + b * HID + tid] = c;
            }
        }
        __syncthreads();
    }
}

// ---------------------------------------------------------------------------
// Heads: logits (4096x6) and value (4096x1) from g_hs.
// ---------------------------------------------------------------------------
__global__ __launch_bounds__(256) void heads_kernel(const float* __restrict__ Wa,
                                                    const float* __restrict__ ba,
                                                    const float* __restrict__ Wc,
                                                    const float* __restrict__ bc,
                                                    float* __restrict__ out) {
    __shared__ float was[6 * 128];
    __shared__ float wcs[128];
    __shared__ float bas[6];
    __shared__ float bcs;
    const int tid = threadIdx.x;
    for (int i = tid; i < 768; i += 256) was[i] = Wa[i];
    if (tid < 128) wcs[tid] = Wc[tid];
    if (tid < 6) bas[tid] = ba[tid];
    if (tid == 0) bcs = bc[0];
    __syncthreads();

    const int row = blockIdx.x * 256 + tid;
    const float* hp = &g_hs[(size_t)row * 128];
    float acc[6] = {0.f, 0.f, 0.f, 0.f, 0.f, 0.f};
    float accv = 0.f;
    for (int k = 0; k < 128; k += 4) {
        const float4 h4 = *(const float4*)&hp[k];
#pragma unroll
        for (int a = 0; a < 6; a++) {
            const float4 w4 = *(const float4*)&was[a * 128 + k];
            acc[a] += h4.x * w4.x + h4.y * w4.y + h4.z * w4.z + h4.w * w4.w;
        }
        const float4 wc4 = *(const float4*)&wcs[k];
        accv += h4.x * wc4.x + h4.y * wc4.y + h4.z * wc4.z + h4.w * wc4.w;
    }
#pragma unroll
    for (int a = 0; a < 6; a++) out[row * 6 + a] = acc[a] + bas[a];
    out[24576 + row] = accv + bcs;
}

// ---------------------------------------------------------------------------
// Launch
// ---------------------------------------------------------------------------
extern "C" void kernel_launch(void* const* d_in, const int* in_sizes, int n_in,
                              void* d_out, int out_size) {
    const float* x    = (const float*)d_in[0];
    const float* done = (const float*)d_in[1];
    const float* h0   = (const float*)d_in[2];
    const float* c0   = (const float*)d_in[3];
    const float* W1   = (const float*)d_in[4];
    const float* b1   = (const float*)d_in[5];
    const float* W2   = (const float*)d_in[6];
    const float* b2   = (const float*)d_in[7];
    const float* W3   = (const float*)d_in[8];
    const float* b3   = (const float*)d_in[9];
    const float* Wfc  = (const float*)d_in[10];
    const float* bfc  = (const float*)d_in[11];
    const float* W_ih = (const float*)d_in[12];
    const float* W_hh = (const float*)d_in[13];
    const float* b_ih = (const float*)d_in[14];
    const float* b_hh = (const float*)d_in[15];
    const float* Wa   = (const float*)d_in[16];
    const float* ba   = (const float*)d_in[17];
    const float* Wc   = (const float*)d_in[18];
    const float* bc   = (const float*)d_in[19];
    float* out = (float*)d_out;

    whh_transpose_kernel<<<128, 512>>>(W_hh);
    conv1_kernel<<<NIMG, 512>>>(x, W1, b1);
    conv2_kernel<<<NIMG, 224>>>(W2, b2);
    conv3_kernel<<<NIMG, 128>>>(W3, b3);
    fc_gemm_kernel<<<dim3(8, 64), 256>>>(Wfc, bfc);
    gates_gemm_kernel<<<dim3(8, 64), 256>>>(W_ih, b_ih, b_hh);
    lstm_kernel<<<BATCH, 512>>>(done, h0, c0, out);
    heads_kernel<<<16, 256>>>(Wa, ba, Wc, bc, out);
}

// round 7
// speedup vs baseline: 2.3836x; 2.3836x over previous
#include <cuda_runtime.h>
#include <cstdint>

#define NIMG   4096
#define TSTEPS 128
#define BATCH  32
#define HID    128

// Scratch (device globals; no allocation allowed)
__device__ float g_z1[(size_t)NIMG * 4 * 400 * 8];    // conv1 out [n][c=ic/8][pix400][ic%8]
__device__ float g_z2[(size_t)NIMG * 4 * 81 * 16];    // conv2 out [n][cc=oc/16][pix81][oc%16]
__device__ float g_z3[(size_t)NIMG * 3136];           // conv3 out, NCHW flatten
__device__ float g_hidden[(size_t)NIMG * 512];        // FC out
__device__ float g_gates[(size_t)NIMG * 512];         // x-proj of gates (+both biases)
__device__ float g_hs[(size_t)NIMG * HID];            // per-step hidden outputs
__device__ float g_whhT[HID * 512];                   // W_hh transposed
__device__ float g_w2t[512 * 64];                     // W2 in [k][oc], k=(c*16+k16)*8+icl
__device__ float g_w3t[576 * 64];                     // W3 in [k][oc], k=(icc*9+k9)*16+icl

// ---------------------------------------------------------------------------
// conv1: 1x84x84 -> 32x20x20, k=8, s=4. One block per image (r2 float4 version)
// ---------------------------------------------------------------------------
__global__ __launch_bounds__(512) void conv1_kernel(const float* __restrict__ x,
                                                    const float* __restrict__ W1,
                                                    const float* __restrict__ b1) {
    __shared__ float img[84 * 84];
    __shared__ float ws[64 * 32];   // [k][oc]
    __shared__ float bs[32];
    const int n = blockIdx.x;
    const int tid = threadIdx.x;
    const float* xin = x + (size_t)n * 7056;
    for (int i = tid; i < 7056; i += 512) img[i] = xin[i] * (1.0f / 255.0f);
    for (int i = tid; i < 2048; i += 512) {
        int k = i >> 5, oc = i & 31;
        ws[i] = W1[oc * 64 + k];
    }
    if (tid < 32) bs[tid] = b1[tid];
    __syncthreads();

    if (tid < 400) {
        const int ocg = tid & 1;
        const int pp  = tid >> 1;
        const int p0  = pp * 2;
        const int oy  = p0 / 20, ox0 = p0 % 20;
        const int iy  = oy * 4,  ix  = ox0 * 4;

        float acc0[16], acc1[16];
#pragma unroll
        for (int o = 0; o < 16; o++) { acc0[o] = 0.f; acc1[o] = 0.f; }

#pragma unroll
        for (int ky = 0; ky < 8; ky++) {
            const float* ip = &img[(iy + ky) * 84 + ix];
            const float4 q0 = *(const float4*)(ip);
            const float4 q1 = *(const float4*)(ip + 4);
            const float4 q2 = *(const float4*)(ip + 8);
            float v[12];
            v[0]=q0.x; v[1]=q0.y; v[2]=q0.z; v[3]=q0.w;
            v[4]=q1.x; v[5]=q1.y; v[6]=q1.z; v[7]=q1.w;
            v[8]=q2.x; v[9]=q2.y; v[10]=q2.z; v[11]=q2.w;
#pragma unroll
            for (int kx = 0; kx < 8; kx++) {
                const float vv0 = v[kx];
                const float vv1 = v[kx + 4];
                const float* wp = &ws[(ky * 8 + kx) * 32 + ocg * 16];
                const float4 w0 = *(const float4*)(wp);
                const float4 w1 = *(const float4*)(wp + 4);
                const float4 w2 = *(const float4*)(wp + 8);
                const float4 w3 = *(const float4*)(wp + 12);
                const float wv[16] = {w0.x,w0.y,w0.z,w0.w, w1.x,w1.y,w1.z,w1.w,
                                      w2.x,w2.y,w2.z,w2.w, w3.x,w3.y,w3.z,w3.w};
#pragma unroll
                for (int o = 0; o < 16; o++) {
                    acc0[o] += vv0 * wv[o];
                    acc1[o] += vv1 * wv[o];
                }
            }
        }
        float* zp = g_z1 + (size_t)n * 12800;
#pragma unroll
        for (int o = 0; o < 16; o++) {
            const int oc = ocg * 16 + o;
            const int g = oc >> 3, l = oc & 7;
            zp[(g * 400 + p0) * 8 + l]     = fmaxf(acc0[o] + bs[oc], 0.f);
            zp[(g * 400 + p0 + 1) * 8 + l] = fmaxf(acc1[o] + bs[oc], 0.f);
        }
    }
}

// ---------------------------------------------------------------------------
// Weight re-layout preps
// ---------------------------------------------------------------------------
__global__ __launch_bounds__(256) void w2t_kernel(const float* __restrict__ W2) {
    const int id = blockIdx.x * 256 + threadIdx.x;   // 0..32767
    const int k = id >> 6, oc = id & 63;
    const int c = k >> 7, k16 = (k & 127) >> 3, icl = k & 7;
    g_w2t[k * 64 + oc] = W2[oc * 512 + (c * 8 + icl) * 16 + k16];
}
__global__ __launch_bounds__(256) void w3t_kernel(const float* __restrict__ W3) {
    const int id = blockIdx.x * 256 + threadIdx.x;   // 0..36863
    const int k = id >> 6, oc = id & 63;
    const int icc = k / 144, rem = k % 144, k9 = rem >> 4, icl = rem & 15;
    g_w3t[k * 64 + oc] = W3[oc * 576 + (icc * 16 + icl) * 9 + k9];
}
__global__ __launch_bounds__(512) void whh_transpose_kernel(const float* __restrict__ W_hh) {
    const int id = blockIdx.x * 512 + threadIdx.x;   // 0..65535
    const int k = id >> 9, j = id & 511;
    g_whhT[k * 512 + j] = W_hh[j * 128 + k];
}

// ---------------------------------------------------------------------------
// conv2 as implicit GEMM: M=331776 (=5184*64 rows=(n,p)), K=512, N=64 oc.
// A[m,k] = z1[n][c][(oy*2+ky)*20+ox*2+kx][icl],  k=(c*16+k16)*8+icl.
// ---------------------------------------------------------------------------
__global__ __launch_bounds__(256) void conv2_gemm_kernel(const float* __restrict__ b2) {
    __shared__ float As[16 * 68];
    __shared__ float Bs[16 * 68];
    const int tid = threadIdx.x;
    const int m0 = blockIdx.x * 64;
    // A-load role
    const int ar = tid >> 2, ac = (tid & 3) << 2;
    const int m = m0 + ar;
    const int an = m / 81, ap = m % 81;
    const int aiy = (ap / 9) * 2, aix = (ap % 9) * 2;
    // B-load role
    const int kb = tid >> 4, ob = (tid & 15) << 2;
    // compute role
    const int tx = tid & 15, ty = tid >> 4;

    float acc[4][4];
#pragma unroll
    for (int i = 0; i < 4; i++)
#pragma unroll
        for (int j = 0; j < 4; j++) acc[i][j] = 0.f;

    for (int k0 = 0; k0 < 512; k0 += 16) {
        const int k = k0 + ac;
        const int c = k >> 7, k16 = (k & 127) >> 3, icl = k & 7;
        const int ky = k16 >> 2, kx = k16 & 3;
        const float4 av = *(const float4*)&g_z1[
            (((size_t)an * 4 + c) * 400 + (aiy + ky) * 20 + aix + kx) * 8 + icl];
        As[(ac + 0) * 68 + ar] = av.x;
        As[(ac + 1) * 68 + ar] = av.y;
        As[(ac + 2) * 68 + ar] = av.z;
        As[(ac + 3) * 68 + ar] = av.w;
        const float4 bv = *(const float4*)&g_w2t[(size_t)(k0 + kb) * 64 + ob];
        *(float4*)&Bs[kb * 68 + ob] = bv;
        __syncthreads();
#pragma unroll
        for (int kk = 0; kk < 16; kk++) {
            const float4 a = *(const float4*)&As[kk * 68 + (ty << 2)];
            const float4 b = *(const float4*)&Bs[kk * 68 + (tx << 2)];
            acc[0][0] += a.x * b.x; acc[0][1] += a.x * b.y;
            acc[0][2] += a.x * b.z; acc[0][3] += a.x * b.w;
            acc[1][0] += a.y * b.x; acc[1][1] += a.y * b.y;
            acc[1][2] += a.y * b.z; acc[1][3] += a.y * b.w;
            acc[2][0] += a.z * b.x; acc[2][1] += a.z * b.y;
            acc[2][2] += a.z * b.z; acc[2][3] += a.z * b.w;
            acc[3][0] += a.w * b.x; acc[3][1] += a.w * b.y;
            acc[3][2] += a.w * b.z; acc[3][3] += a.w * b.w;
        }
        __syncthreads();
    }

    const int oc0 = tx << 2;
    const int ocg = oc0 >> 4, ocl = oc0 & 15;
    float4 bb = *(const float4*)&b2[oc0];
#pragma unroll
    for (int i = 0; i < 4; i++) {
        const int mm = m0 + (ty << 2) + i;
        const int n = mm / 81, p = mm % 81;
        float4 o;
        o.x = fmaxf(acc[i][0] + bb.x, 0.f);
        o.y = fmaxf(acc[i][1] + bb.y, 0.f);
        o.z = fmaxf(acc[i][2] + bb.z, 0.f);
        o.w = fmaxf(acc[i][3] + bb.w, 0.f);
        *(float4*)&g_z2[(((size_t)n * 4 + ocg) * 81 + p) * 16 + ocl] = o;
    }
}

// ---------------------------------------------------------------------------
// conv3 as implicit GEMM: M=200704 (=3136*64 rows=(n,p)), K=576, N=64 oc.
// A[m,k] = z2[n][icc][(oy+ky)*9+ox+kx][icl],  k=(icc*9+k9)*16+icl.
// ---------------------------------------------------------------------------
__global__ __launch_bounds__(256) void conv3_gemm_kernel(const float* __restrict__ b3) {
    __shared__ float As[16 * 68];
    __shared__ float Bs[16 * 68];
    const int tid = threadIdx.x;
    const int m0 = blockIdx.x * 64;
    const int ar = tid >> 2, ac = (tid & 3) << 2;
    const int m = m0 + ar;
    const int an = m / 49, ap = m % 49;
    const int aoy = ap / 7, aox = ap % 7;
    const int kb = tid >> 4, ob = (tid & 15) << 2;
    const int tx = tid & 15, ty = tid >> 4;

    float acc[4][4];
#pragma unroll
    for (int i = 0; i < 4; i++)
#pragma unroll
        for (int j = 0; j < 4; j++) acc[i][j] = 0.f;

    for (int k0 = 0; k0 < 576; k0 += 16) {
        const int k = k0 + ac;
        const int icc = k / 144, rem = k % 144;
        const int k9 = rem >> 4, icl = rem & 15;
        const int ky = k9 / 3, kx = k9 % 3;
        const float4 av = *(const float4*)&g_z2[
            (((size_t)an * 4 + icc) * 81 + (aoy + ky) * 9 + aox + kx) * 16 + icl];
        As[(ac + 0) * 68 + ar] = av.x;
        As[(ac + 1) * 68 + ar] = av.y;
        As[(ac + 2) * 68 + ar] = av.z;
        As[(ac + 3) * 68 + ar] = av.w;
        const float4 bv = *(const float4*)&g_w3t[(size_t)(k0 + kb) * 64 + ob];
        *(float4*)&Bs[kb * 68 + ob] = bv;
        __syncthreads();
#pragma unroll
        for (int kk = 0; kk < 16; kk++) {
            const float4 a = *(const float4*)&As[kk * 68 + (ty << 2)];
            const float4 b = *(const float4*)&Bs[kk * 68 + (tx << 2)];
            acc[0][0] += a.x * b.x; acc[0][1] += a.x * b.y;
            acc[0][2] += a.x * b.z; acc[0][3] += a.x * b.w;
            acc[1][0] += a.y * b.x; acc[1][1] += a.y * b.y;
            acc[1][2] += a.y * b.z; acc[1][3] += a.y * b.w;
            acc[2][0] += a.z * b.x; acc[2][1] += a.z * b.y;
            acc[2][2] += a.z * b.z; acc[2][3] += a.z * b.w;
            acc[3][0] += a.w * b.x; acc[3][1] += a.w * b.y;
            acc[3][2] += a.w * b.z; acc[3][3] += a.w * b.w;
        }
        __syncthreads();
    }

    const int oc0 = tx << 2;
    float4 bb = *(const float4*)&b3[oc0];
    const float bbv[4] = {bb.x, bb.y, bb.z, bb.w};
#pragma unroll
    for (int i = 0; i < 4; i++) {
        const int mm = m0 + (ty << 2) + i;
        const int n = mm / 49, p = mm % 49;
        float* zp = &g_z3[(size_t)n * 3136 + oc0 * 49 + p];
#pragma unroll
        for (int j = 0; j < 4; j++)
            zp[j * 49] = fmaxf(acc[i][j] + bbv[j], 0.f);
    }
}

// ---------------------------------------------------------------------------
// GEMM: C[M,N] = A[M,K] * B[N,K]^T + bias(+bias2), optional relu. (r1 proven)
// ---------------------------------------------------------------------------
__device__ __forceinline__ void gemm_body(const float* __restrict__ A,
                                          const float* __restrict__ B,
                                          float* __restrict__ C, int K,
                                          const float* __restrict__ bias1,
                                          const float* __restrict__ bias2,
                                          bool relu) {
    __shared__ float As[16 * 68];
    __shared__ float Bs[16 * 68];
    const int tid = threadIdx.x;
    const int m0 = blockIdx.y * 64, n0 = blockIdx.x * 64;
    const int ar = tid >> 2, ac = (tid & 3) << 2;
    const int tx = tid & 15, ty = tid >> 4;
    const int N = 512;

    float acc[4][4];
#pragma unroll
    for (int i = 0; i < 4; i++)
#pragma unroll
        for (int j = 0; j < 4; j++) acc[i][j] = 0.f;

    const float* Ap = A + (size_t)(m0 + ar) * K + ac;
    const float* Bp = B + (size_t)(n0 + ar) * K + ac;

    for (int k0 = 0; k0 < K; k0 += 16) {
        const float4 av = *(const float4*)(Ap + k0);
        const float4 bv = *(const float4*)(Bp + k0);
        As[(ac + 0) * 68 + ar] = av.x;
        As[(ac + 1) * 68 + ar] = av.y;
        As[(ac + 2) * 68 + ar] = av.z;
        As[(ac + 3) * 68 + ar] = av.w;
        Bs[(ac + 0) * 68 + ar] = bv.x;
        Bs[(ac + 1) * 68 + ar] = bv.y;
        Bs[(ac + 2) * 68 + ar] = bv.z;
        Bs[(ac + 3) * 68 + ar] = bv.w;
        __syncthreads();
#pragma unroll
        for (int kk = 0; kk < 16; kk++) {
            const float4 a = *(const float4*)&As[kk * 68 + (ty << 2)];
            const float4 b = *(const float4*)&Bs[kk * 68 + (tx << 2)];
            acc[0][0] += a.x * b.x; acc[0][1] += a.x * b.y;
            acc[0][2] += a.x * b.z; acc[0][3] += a.x * b.w;
            acc[1][0] += a.y * b.x; acc[1][1] += a.y * b.y;
            acc[1][2] += a.y * b.z; acc[1][3] += a.y * b.w;
            acc[2][0] += a.z * b.x; acc[2][1] += a.z * b.y;
            acc[2][2] += a.z * b.z; acc[2][3] += a.z * b.w;
            acc[3][0] += a.w * b.x; acc[3][1] += a.w * b.y;
            acc[3][2] += a.w * b.z; acc[3][3] += a.w * b.w;
        }
        __syncthreads();
    }

    float bb[4];
#pragma unroll
    for (int j = 0; j < 4; j++) {
        int nn = n0 + (tx << 2) + j;
        bb[j] = bias1[nn] + (bias2 ? bias2[nn] : 0.f);
    }
#pragma unroll
    for (int i = 0; i < 4; i++) {
        float4 o;
        float v0 = acc[i][0] + bb[0], v1 = acc[i][1] + bb[1];
        float v2 = acc[i][2] + bb[2], v3 = acc[i][3] + bb[3];
        if (relu) {
            v0 = fmaxf(v0, 0.f); v1 = fmaxf(v1, 0.f);
            v2 = fmaxf(v2, 0.f); v3 = fmaxf(v3, 0.f);
        }
        o.x = v0; o.y = v1; o.z = v2; o.w = v3;
        *(float4*)&C[(size_t)(m0 + (ty << 2) + i) * N + n0 + (tx << 2)] = o;
    }
}

__global__ __launch_bounds__(256) void fc_gemm_kernel(const float* __restrict__ Wfc,
                                                      const float* __restrict__ bfc) {
    gemm_body(g_z3, Wfc, g_hidden, 3136, bfc, nullptr, true);
}
__global__ __launch_bounds__(256) void gates_gemm_kernel(const float* __restrict__ W_ih,
                                                         const float* __restrict__ b_ih,
                                                         const float* __restrict__ b_hh) {
    gemm_body(g_hidden, W_ih, g_gates, 512, b_ih, b_hh, false);
}

// ---------------------------------------------------------------------------
// LSTM: one block per batch element, 512 threads (r4/5 proven coalesced).
// ---------------------------------------------------------------------------
__device__ __forceinline__ float sigmoidf_(float v) {
    return 1.0f / (1.0f + __expf(-v));
}

__global__ __launch_bounds__(512) void lstm_kernel(const float* __restrict__ done,
                                                   const float* __restrict__ h0,
                                                   const float* __restrict__ c0,
                                                   float* __restrict__ out) {
    __shared__ float hm[HID];
    __shared__ float cs[HID];
    __shared__ float hs[HID];
    __shared__ float part[4 * 512];
    const int b = blockIdx.x;
    const int tid = threadIdx.x;
    const int j4 = tid & 127;
    const int ks = tid >> 7;

    if (tid < HID) {
        hs[tid] = h0[b * HID + tid];
        cs[tid] = c0[b * HID + tid];
    }
    __syncthreads();

    for (int t = 0; t < TSTEPS; t++) {
        const float mask = 1.0f - done[t * BATCH + b];
        if (tid < HID) hm[tid] = hs[tid] * mask;
        __syncthreads();

        float a0 = 0.f, a1 = 0.f, a2 = 0.f, a3 = 0.f;
        const float4* __restrict__ wt = (const float4*)&g_whhT[(ks * 32) * 512] + j4;
        const float* __restrict__ hk = &hm[ks * 32];
#pragma unroll
        for (int kk = 0; kk < 32; kk++) {
            const float4 w = wt[kk * 128];
            const float h = hk[kk];
            a0 += w.x * h; a1 += w.y * h; a2 += w.z * h; a3 += w.w * h;
        }
        float4 pv = {a0, a1, a2, a3};
        *(float4*)&part[ks * 512 + j4 * 4] = pv;
        __syncthreads();

        const float gx = g_gates[(size_t)(t * BATCH + b) * 512 + tid];
        const float gsum = part[tid] + part[512 + tid] + part[1024 + tid] +
                           part[1536 + tid] + gx;
        part[tid] = gsum;
        __syncthreads();

        if (tid < HID) {
            const float gi = part[tid];
            const float gf = part[tid + 128];
            const float gc = part[tid + 256];
            const float go = part[tid + 384];
            float c = cs[tid] * mask;
            c = sigmoidf_(gf) * c + sigmoidf_(gi) * tanhf(gc);
            const float h = sigmoidf_(go) * tanhf(c);
            cs[tid] = c;
            hs[tid] = h;
            g_hs[(size_t)(t * BATCH + b) * HID + tid] = h;
            if (t == TSTEPS - 1) {
                out[28672 + b * HID + tid] = h;
                out[32768 + b * HID + tid] = c;
            }
        }
        __syncthreads();
    }
}

// ---------------------------------------------------------------------------
// Heads: logits (4096x6) and value (4096x1) from g_hs.
// ---------------------------------------------------------------------------
__global__ __launch_bounds__(256) void heads_kernel(const float* __restrict__ Wa,
                                                    const float* __restrict__ ba,
                                                    const float* __restrict__ Wc,
                                                    const float* __restrict__ bc,
                                                    float* __restrict__ out) {
    __shared__ float was[6 * 128];
    __shared__ float wcs[128];
    __shared__ float bas[6];
    __shared__ float bcs;
    const int tid = threadIdx.x;
    for (int i = tid; i < 768; i += 256) was[i] = Wa[i];
    if (tid < 128) wcs[tid] = Wc[tid];
    if (tid < 6) bas[tid] = ba[tid];
    if (tid == 0) bcs = bc[0];
    __syncthreads();

    const int row = blockIdx.x * 256 + tid;
    const float* hp = &g_hs[(size_t)row * 128];
    float acc[6] = {0.f, 0.f, 0.f, 0.f, 0.f, 0.f};
    float accv = 0.f;
    for (int k = 0; k < 128; k += 4) {
        const float4 h4 = *(const float4*)&hp[k];
#pragma unroll
        for (int a = 0; a < 6; a++) {
            const float4 w4 = *(const float4*)&was[a * 128 + k];
            acc[a] += h4.x * w4.x + h4.y * w4.y + h4.z * w4.z + h4.w * w4.w;
        }
        const float4 wc4 = *(const float4*)&wcs[k];
        accv += h4.x * wc4.x + h4.y * wc4.y + h4.z * wc4.z + h4.w * wc4.w;
    }
#pragma unroll
    for (int a = 0; a < 6; a++) out[row * 6 + a] = acc[a] + bas[a];
    out[24576 + row] = accv + bcs;
}

// ---------------------------------------------------------------------------
// Launch
// ---------------------------------------------------------------------------
extern "C" void kernel_launch(void* const* d_in, const int* in_sizes, int n_in,
                              void* d_out, int out_size) {
    const float* x    = (const float*)d_in[0];
    const float* done = (const float*)d_in[1];
    const float* h0   = (const float*)d_in[2];
    const float* c0   = (const float*)d_in[3];
    const float* W1   = (const float*)d_in[4];
    const float* b1   = (const float*)d_in[5];
    const float* W2   = (const float*)d_in[6];
    const float* b2   = (const float*)d_in[7];
    const float* W3   = (const float*)d_in[8];
    const float* b3   = (const float*)d_in[9];
    const float* Wfc  = (const float*)d_in[10];
    const float* bfc  = (const float*)d_in[11];
    const float* W_ih = (const float*)d_in[12];
    const float* W_hh = (const float*)d_in[13];
    const float* b_ih = (const float*)d_in[14];
    const float* b_hh = (const float*)d_in[15];
    const float* Wa   = (const float*)d_in[16];
    const float* ba   = (const float*)d_in[17];
    const float* Wc   = (const float*)d_in[18];
    const float* bc   = (const float*)d_in[19];
    float* out = (float*)d_out;

    whh_transpose_kernel<<<128, 512>>>(W_hh);
    w2t_kernel<<<128, 256>>>(W2);
    w3t_kernel<<<144, 256>>>(W3);
    conv1_kernel<<<NIMG, 512>>>(x, W1, b1);
    conv2_gemm_kernel<<<5184, 256>>>(b2);
    conv3_gemm_kernel<<<3136, 256>>>(b3);
    fc_gemm_kernel<<<dim3(8, 64), 256>>>(Wfc, bfc);
    gates_gemm_kernel<<<dim3(8, 64), 256>>>(W_ih, b_ih, b_hh);
    lstm_kernel<<<BATCH, 512>>>(done, h0, c0, out);
    heads_kernel<<<16, 256>>>(Wa, ba, Wc, bc, out);
}

// round 8
// speedup vs baseline: 2.8346x; 1.1892x over previous
#include <cuda_runtime.h>
#include <cstdint>

#define NIMG   4096
#define TSTEPS 128
#define BATCH  32
#define HID    128

// Scratch (device globals; no allocation allowed)
__device__ float g_z1[(size_t)NIMG * 4 * 400 * 8];    // conv1 out [n][c=ic/8][pix400][ic%8]
__device__ float g_z2[(size_t)NIMG * 4 * 81 * 16];    // conv2 out [n][cc=oc/16][pix81][oc%16]
__device__ float g_z3[(size_t)NIMG * 3136];           // conv3 out, NCHW flatten
__device__ float g_hidden[(size_t)NIMG * 512];        // FC out
__device__ float g_gates[(size_t)NIMG * 512];         // x-proj of gates (+both biases)
__device__ float g_hs[(size_t)NIMG * HID];            // per-step hidden outputs
__device__ float g_whhT[HID * 512];                   // W_hh transposed
__device__ float g_w1t[64 * 32];                      // W1/255 in [k][oc]
__device__ float g_w2t[512 * 64];                     // W2 in [k][oc]
__device__ float g_w3t[576 * 64];                     // W3 in [k][oc]

// ---------------------------------------------------------------------------
// Weight re-layout preps
// ---------------------------------------------------------------------------
__global__ __launch_bounds__(256) void w1t_kernel(const float* __restrict__ W1) {
    const int id = blockIdx.x * 256 + threadIdx.x;   // 0..2047
    const int k = id >> 5, oc = id & 31;
    g_w1t[k * 32 + oc] = W1[oc * 64 + k] * (1.0f / 255.0f);
}
__global__ __launch_bounds__(256) void w2t_kernel(const float* __restrict__ W2) {
    const int id = blockIdx.x * 256 + threadIdx.x;   // 0..32767
    const int k = id >> 6, oc = id & 63;
    const int c = k >> 7, k16 = (k & 127) >> 3, icl = k & 7;
    g_w2t[k * 64 + oc] = W2[oc * 512 + (c * 8 + icl) * 16 + k16];
}
__global__ __launch_bounds__(256) void w3t_kernel(const float* __restrict__ W3) {
    const int id = blockIdx.x * 256 + threadIdx.x;   // 0..36863
    const int k = id >> 6, oc = id & 63;
    const int icc = k / 144, rem = k % 144, k9 = rem >> 4, icl = rem & 15;
    g_w3t[k * 64 + oc] = W3[oc * 576 + (icc * 16 + icl) * 9 + k9];
}
__global__ __launch_bounds__(512) void whh_transpose_kernel(const float* __restrict__ W_hh) {
    const int id = blockIdx.x * 512 + threadIdx.x;   // 0..65535
    const int k = id >> 9, j = id & 511;
    g_whhT[k * 512 + j] = W_hh[j * 128 + k];
}

// ---------------------------------------------------------------------------
// 16-deep k-slab microkernel: 4x4 accум from As[k][m] / Bs[k][n] (stride 68)
// ---------------------------------------------------------------------------
__device__ __forceinline__ void mm16(const float* __restrict__ As,
                                     const float* __restrict__ Bs,
                                     int ty, int tx, float acc[4][4]) {
#pragma unroll
    for (int kk = 0; kk < 16; kk++) {
        const float4 a = *(const float4*)&As[kk * 68 + (ty << 2)];
        const float4 b = *(const float4*)&Bs[kk * 68 + (tx << 2)];
        acc[0][0] += a.x * b.x; acc[0][1] += a.x * b.y;
        acc[0][2] += a.x * b.z; acc[0][3] += a.x * b.w;
        acc[1][0] += a.y * b.x; acc[1][1] += a.y * b.y;
        acc[1][2] += a.y * b.z; acc[1][3] += a.y * b.w;
        acc[2][0] += a.z * b.x; acc[2][1] += a.z * b.y;
        acc[2][2] += a.z * b.z; acc[2][3] += a.z * b.w;
        acc[3][0] += a.w * b.x; acc[3][1] += a.w * b.y;
        acc[3][2] += a.w * b.z; acc[3][3] += a.w * b.w;
    }
}

#define STORE_A(buf, ac, ar, v)                 \
    As[buf][(ac + 0) * 68 + ar] = v.x;          \
    As[buf][(ac + 1) * 68 + ar] = v.y;          \
    As[buf][(ac + 2) * 68 + ar] = v.z;          \
    As[buf][(ac + 3) * 68 + ar] = v.w;

// ---------------------------------------------------------------------------
// conv1 as implicit GEMM: M=1638400 rows (n,p), N=32 oc, K=64 (8x8 kernel).
// 1/255 folded into g_w1t. BM=128, BN=32, BK=16, 256 threads, 4x4 microtile.
// ---------------------------------------------------------------------------
__global__ __launch_bounds__(256) void conv1_gemm_kernel(const float* __restrict__ x,
                                                         const float* __restrict__ b1) {
    __shared__ float As[16 * 132];   // [kk][row 0..127] pad 132
    __shared__ float Bs[16 * 36];    // [kk][oc 0..31]  pad 36
    const int tid = threadIdx.x;
    const int m0 = blockIdx.x * 128;
    // A role: each thread loads 8 consecutive k (one image row segment)
    const int ar = tid >> 1, q = tid & 1;
    const int m = m0 + ar;
    const int an = m / 400, ap = m % 400;
    const int iy = (ap / 20) * 4, ix = (ap % 20) * 4;
    const float* xrow = x + (size_t)an * 7056 + ix;
    // B role: threads 0..127
    const int kb = tid >> 3, ob = (tid & 7) << 2;
    // compute role
    const int tx = tid & 7, ty = tid >> 3;   // ty 0..31

    float acc[4][4];
#pragma unroll
    for (int i = 0; i < 4; i++)
#pragma unroll
        for (int j = 0; j < 4; j++) acc[i][j] = 0.f;

    for (int k0 = 0; k0 < 64; k0 += 16) {
        const int ky = (k0 >> 3) + q;
        const float* xp = xrow + (iy + ky) * 84;
        const float4 v0 = *(const float4*)(xp);
        const float4 v1 = *(const float4*)(xp + 4);
        float4 bvec;
        if (tid < 128) bvec = *(const float4*)&g_w1t[(k0 + kb) * 32 + ob];
        __syncthreads();   // previous slab fully consumed
        const int kkb = q * 8;
        As[(kkb + 0) * 132 + ar] = v0.x;
        As[(kkb + 1) * 132 + ar] = v0.y;
        As[(kkb + 2) * 132 + ar] = v0.z;
        As[(kkb + 3) * 132 + ar] = v0.w;
        As[(kkb + 4) * 132 + ar] = v1.x;
        As[(kkb + 5) * 132 + ar] = v1.y;
        As[(kkb + 6) * 132 + ar] = v1.z;
        As[(kkb + 7) * 132 + ar] = v1.w;
        if (tid < 128) *(float4*)&Bs[kb * 36 + ob] = bvec;
        __syncthreads();
#pragma unroll
        for (int kk = 0; kk < 16; kk++) {
            const float4 a = *(const float4*)&As[kk * 132 + (ty << 2)];
            const float4 b = *(const float4*)&Bs[kk * 36 + (tx << 2)];
            acc[0][0] += a.x * b.x; acc[0][1] += a.x * b.y;
            acc[0][2] += a.x * b.z; acc[0][3] += a.x * b.w;
            acc[1][0] += a.y * b.x; acc[1][1] += a.y * b.y;
            acc[1][2] += a.y * b.z; acc[1][3] += a.y * b.w;
            acc[2][0] += a.z * b.x; acc[2][1] += a.z * b.y;
            acc[2][2] += a.z * b.z; acc[2][3] += a.z * b.w;
            acc[3][0] += a.w * b.x; acc[3][1] += a.w * b.y;
            acc[3][2] += a.w * b.z; acc[3][3] += a.w * b.w;
        }
    }

    const int oc0 = tx << 2;
    const int g = oc0 >> 3, l = oc0 & 7;
    const float4 bb = *(const float4*)&b1[oc0];
#pragma unroll
    for (int i = 0; i < 4; i++) {
        const int mm = m0 + (ty << 2) + i;
        const int n = mm / 400, p = mm % 400;
        float4 o;
        o.x = fmaxf(acc[i][0] + bb.x, 0.f);
        o.y = fmaxf(acc[i][1] + bb.y, 0.f);
        o.z = fmaxf(acc[i][2] + bb.z, 0.f);
        o.w = fmaxf(acc[i][3] + bb.w, 0.f);
        *(float4*)&g_z1[((size_t)n * 4 + g) * 3200 + p * 8 + l] = o;
    }
}

// ---------------------------------------------------------------------------
// conv2 as implicit GEMM, double-buffered: M=331776, K=512, N=64.
// ---------------------------------------------------------------------------
__global__ __launch_bounds__(256) void conv2_gemm_kernel(const float* __restrict__ b2) {
    __shared__ float As[2][16 * 68];
    __shared__ float Bs[2][16 * 68];
    const int tid = threadIdx.x;
    const int m0 = blockIdx.x * 64;
    const int ar = tid >> 2, ac = (tid & 3) << 2;
    const int m = m0 + ar;
    const int an = m / 81, ap = m % 81;
    const int aiy = (ap / 9) * 2, aix = (ap % 9) * 2;
    const int kb = tid >> 4, ob = (tid & 15) << 2;
    const int tx = tid & 15, ty = tid >> 4;

    float acc[4][4];
#pragma unroll
    for (int i = 0; i < 4; i++)
#pragma unroll
        for (int j = 0; j < 4; j++) acc[i][j] = 0.f;

    // prologue: chunk 0
    {
        const int k = ac;
        const int c = k >> 7, k16 = (k & 127) >> 3, icl = k & 7;
        const int ky = k16 >> 2, kx = k16 & 3;
        const float4 av = *(const float4*)&g_z1[
            (((size_t)an * 4 + c) * 400 + (aiy + ky) * 20 + aix + kx) * 8 + icl];
        STORE_A(0, ac, ar, av);
        *(float4*)&Bs[0][kb * 68 + ob] = *(const float4*)&g_w2t[(size_t)kb * 64 + ob];
    }
    __syncthreads();

    int buf = 0;
    for (int k0 = 16; k0 < 512; k0 += 16) {
        const int k = k0 + ac;
        const int c = k >> 7, k16 = (k & 127) >> 3, icl = k & 7;
        const int ky = k16 >> 2, kx = k16 & 3;
        const float4 av = *(const float4*)&g_z1[
            (((size_t)an * 4 + c) * 400 + (aiy + ky) * 20 + aix + kx) * 8 + icl];
        const float4 bv = *(const float4*)&g_w2t[(size_t)(k0 + kb) * 64 + ob];
        mm16(As[buf], Bs[buf], ty, tx, acc);
        STORE_A(buf ^ 1, ac, ar, av);
        *(float4*)&Bs[buf ^ 1][kb * 68 + ob] = bv;
        __syncthreads();
        buf ^= 1;
    }
    mm16(As[buf], Bs[buf], ty, tx, acc);

    const int oc0 = tx << 2;
    const int ocg = oc0 >> 4, ocl = oc0 & 15;
    const float4 bb = *(const float4*)&b2[oc0];
#pragma unroll
    for (int i = 0; i < 4; i++) {
        const int mm = m0 + (ty << 2) + i;
        const int n = mm / 81, p = mm % 81;
        float4 o;
        o.x = fmaxf(acc[i][0] + bb.x, 0.f);
        o.y = fmaxf(acc[i][1] + bb.y, 0.f);
        o.z = fmaxf(acc[i][2] + bb.z, 0.f);
        o.w = fmaxf(acc[i][3] + bb.w, 0.f);
        *(float4*)&g_z2[(((size_t)n * 4 + ocg) * 81 + p) * 16 + ocl] = o;
    }
}

// ---------------------------------------------------------------------------
// conv3 as implicit GEMM, double-buffered: M=200704, K=576, N=64.
// ---------------------------------------------------------------------------
__global__ __launch_bounds__(256) void conv3_gemm_kernel(const float* __restrict__ b3) {
    __shared__ float As[2][16 * 68];
    __shared__ float Bs[2][16 * 68];
    const int tid = threadIdx.x;
    const int m0 = blockIdx.x * 64;
    const int ar = tid >> 2, ac = (tid & 3) << 2;
    const int m = m0 + ar;
    const int an = m / 49, ap = m % 49;
    const int aoy = ap / 7, aox = ap % 7;
    const int kb = tid >> 4, ob = (tid & 15) << 2;
    const int tx = tid & 15, ty = tid >> 4;

    float acc[4][4];
#pragma unroll
    for (int i = 0; i < 4; i++)
#pragma unroll
        for (int j = 0; j < 4; j++) acc[i][j] = 0.f;

    {
        const int k = ac;
        const int icc = k / 144, rem = k % 144;
        const int k9 = rem >> 4, icl = rem & 15;
        const int ky = k9 / 3, kx = k9 % 3;
        const float4 av = *(const float4*)&g_z2[
            (((size_t)an * 4 + icc) * 81 + (aoy + ky) * 9 + aox + kx) * 16 + icl];
        STORE_A(0, ac, ar, av);
        *(float4*)&Bs[0][kb * 68 + ob] = *(const float4*)&g_w3t[(size_t)kb * 64 + ob];
    }
    __syncthreads();

    int buf = 0;
    for (int k0 = 16; k0 < 576; k0 += 16) {
        const int k = k0 + ac;
        const int icc = k / 144, rem = k % 144;
        const int k9 = rem >> 4, icl = rem & 15;
        const int ky = k9 / 3, kx = k9 % 3;
        const float4 av = *(const float4*)&g_z2[
            (((size_t)an * 4 + icc) * 81 + (aoy + ky) * 9 + aox + kx) * 16 + icl];
        const float4 bv = *(const float4*)&g_w3t[(size_t)(k0 + kb) * 64 + ob];
        mm16(As[buf], Bs[buf], ty, tx, acc);
        STORE_A(buf ^ 1, ac, ar, av);
        *(float4*)&Bs[buf ^ 1][kb * 68 + ob] = bv;
        __syncthreads();
        buf ^= 1;
    }
    mm16(As[buf], Bs[buf], ty, tx, acc);

    const int oc0 = tx << 2;
    const float4 bb = *(const float4*)&b3[oc0];
    const float bbv[4] = {bb.x, bb.y, bb.z, bb.w};
#pragma unroll
    for (int i = 0; i < 4; i++) {
        const int mm = m0 + (ty << 2) + i;
        const int n = mm / 49, p = mm % 49;
        float* zp = &g_z3[(size_t)n * 3136 + oc0 * 49 + p];
#pragma unroll
        for (int j = 0; j < 4; j++)
            zp[j * 49] = fmaxf(acc[i][j] + bbv[j], 0.f);
    }
}

// ---------------------------------------------------------------------------
// Dense GEMM (fc / gates), double-buffered: C = A[M,K] B[N,K]^T (+biases)
// ---------------------------------------------------------------------------
__device__ __forceinline__ void gemm_db(const float* __restrict__ A,
                                        const float* __restrict__ B,
                                        float* __restrict__ C, int K,
                                        const float* __restrict__ bias1,
                                        const float* __restrict__ bias2,
                                        bool relu) {
    __shared__ float As[2][16 * 68];
    __shared__ float Bs[2][16 * 68];
    const int tid = threadIdx.x;
    const int m0 = blockIdx.y * 64, n0 = blockIdx.x * 64;
    const int ar = tid >> 2, ac = (tid & 3) << 2;
    const int tx = tid & 15, ty = tid >> 4;

    float acc[4][4];
#pragma unroll
    for (int i = 0; i < 4; i++)
#pragma unroll
        for (int j = 0; j < 4; j++) acc[i][j] = 0.f;

    const float* Ap = A + (size_t)(m0 + ar) * K + ac;
    const float* Bp = B + (size_t)(n0 + ar) * K + ac;

    {
        const float4 av = *(const float4*)(Ap);
        const float4 bv = *(const float4*)(Bp);
        STORE_A(0, ac, ar, av);
        Bs[0][(ac + 0) * 68 + ar] = bv.x;
        Bs[0][(ac + 1) * 68 + ar] = bv.y;
        Bs[0][(ac + 2) * 68 + ar] = bv.z;
        Bs[0][(ac + 3) * 68 + ar] = bv.w;
    }
    __syncthreads();

    int buf = 0;
    for (int k0 = 16; k0 < K; k0 += 16) {
        const float4 av = *(const float4*)(Ap + k0);
        const float4 bv = *(const float4*)(Bp + k0);
        mm16(As[buf], Bs[buf], ty, tx, acc);
        STORE_A(buf ^ 1, ac, ar, av);
        Bs[buf ^ 1][(ac + 0) * 68 + ar] = bv.x;
        Bs[buf ^ 1][(ac + 1) * 68 + ar] = bv.y;
        Bs[buf ^ 1][(ac + 2) * 68 + ar] = bv.z;
        Bs[buf ^ 1][(ac + 3) * 68 + ar] = bv.w;
        __syncthreads();
        buf ^= 1;
    }
    mm16(As[buf], Bs[buf], ty, tx, acc);

    float bb[4];
#pragma unroll
    for (int j = 0; j < 4; j++) {
        int nn = n0 + (tx << 2) + j;
        bb[j] = bias1[nn] + (bias2 ? bias2[nn] : 0.f);
    }
#pragma unroll
    for (int i = 0; i < 4; i++) {
        float4 o;
        float v0 = acc[i][0] + bb[0], v1 = acc[i][1] + bb[1];
        float v2 = acc[i][2] + bb[2], v3 = acc[i][3] + bb[3];
        if (relu) {
            v0 = fmaxf(v0, 0.f); v1 = fmaxf(v1, 0.f);
            v2 = fmaxf(v2, 0.f); v3 = fmaxf(v3, 0.f);
        }
        o.x = v0; o.y = v1; o.z = v2; o.w = v3;
        *(float4*)&C[(size_t)(m0 + (ty << 2) + i) * 512 + n0 + (tx << 2)] = o;
    }
}

__global__ __launch_bounds__(256) void fc_gemm_kernel(const float* __restrict__ Wfc,
                                                      const float* __restrict__ bfc) {
    gemm_db(g_z3, Wfc, g_hidden, 3136, bfc, nullptr, true);
}
__global__ __launch_bounds__(256) void gates_gemm_kernel(const float* __restrict__ W_ih,
                                                         const float* __restrict__ b_ih,
                                                         const float* __restrict__ b_hh) {
    gemm_db(g_hidden, W_ih, g_gates, 512, b_ih, b_hh, false);
}

// ---------------------------------------------------------------------------
// LSTM: one block per batch element, 512 threads (proven coalesced version).
// ---------------------------------------------------------------------------
__device__ __forceinline__ float sigmoidf_(float v) {
    return 1.0f / (1.0f + __expf(-v));
}

__global__ __launch_bounds__(512) void lstm_kernel(const float* __restrict__ done,
                                                   const float* __restrict__ h0,
                                                   const float* __restrict__ c0,
                                                   float* __restrict__ out) {
    __shared__ float hm[HID];
    __shared__ float cs[HID];
    __shared__ float hs[HID];
    __shared__ float part[4 * 512];
    const int b = blockIdx.x;
    const int tid = threadIdx.x;
    const int j4 = tid & 127;
    const int ks = tid >> 7;

    if (tid < HID) {
        hs[tid] = h0[b * HID + tid];
        cs[tid] = c0[b * HID + tid];
    }
    __syncthreads();

    for (int t = 0; t < TSTEPS; t++) {
        const float mask = 1.0f - done[t * BATCH + b];
        if (tid < HID) hm[tid] = hs[tid] * mask;
        __syncthreads();

        float a0 = 0.f, a1 = 0.f, a2 = 0.f, a3 = 0.f;
        const float4* __restrict__ wt = (const float4*)&g_whhT[(ks * 32) * 512] + j4;
        const float* __restrict__ hk = &hm[ks * 32];
#pragma unroll
        for (int kk = 0; kk < 32; kk++) {
            const float4 w = wt[kk * 128];
            const float h = hk[kk];
            a0 += w.x * h; a1 += w.y * h; a2 += w.z * h; a3 += w.w * h;
        }
        float4 pv = {a0, a1, a2, a3};
        *(float4*)&part[ks * 512 + j4 * 4] = pv;
        __syncthreads();

        const float gx = g_gates[(size_t)(t * BATCH + b) * 512 + tid];
        const float gsum = part[tid] + part[512 + tid] + part[1024 + tid] +
                           part[1536 + tid] + gx;
        part[tid] = gsum;
        __syncthreads();

        if (tid < HID) {
            const float gi = part[tid];
            const float gf = part[tid + 128];
            const float gc = part[tid + 256];
            const float go = part[tid + 384];
            float c = cs[tid] * mask;
            c = sigmoidf_(gf) * c + sigmoidf_(gi) * tanhf(gc);
            const float h = sigmoidf_(go) * tanhf(c);
            cs[tid] = c;
            hs[tid] = h;
            g_hs[(size_t)(t * BATCH + b) * HID + tid] = h;
            if (t == TSTEPS - 1) {
                out[28672 + b * HID + tid] = h;
                out[32768 + b * HID + tid] = c;
            }
        }
        __syncthreads();
    }
}

// ---------------------------------------------------------------------------
// Heads: logits (4096x6) and value (4096x1) from g_hs.
// ---------------------------------------------------------------------------
__global__ __launch_bounds__(256) void heads_kernel(const float* __restrict__ Wa,
                                                    const float* __restrict__ ba,
                                                    const float* __restrict__ Wc,
                                                    const float* __restrict__ bc,
                                                    float* __restrict__ out) {
    __shared__ float was[6 * 128];
    __shared__ float wcs[128];
    __shared__ float bas[6];
    __shared__ float bcs;
    const int tid = threadIdx.x;
    for (int i = tid; i < 768; i += 256) was[i] = Wa[i];
    if (tid < 128) wcs[tid] = Wc[tid];
    if (tid < 6) bas[tid] = ba[tid];
    if (tid == 0) bcs = bc[0];
    __syncthreads();

    const int row = blockIdx.x * 256 + tid;
    const float* hp = &g_hs[(size_t)row * 128];
    float acc[6] = {0.f, 0.f, 0.f, 0.f, 0.f, 0.f};
    float accv = 0.f;
    for (int k = 0; k < 128; k += 4) {
        const float4 h4 = *(const float4*)&hp[k];
#pragma unroll
        for (int a = 0; a < 6; a++) {
            const float4 w4 = *(const float4*)&was[a * 128 + k];
            acc[a] += h4.x * w4.x + h4.y * w4.y + h4.z * w4.z + h4.w * w4.w;
        }
        const float4 wc4 = *(const float4*)&wcs[k];
        accv += h4.x * wc4.x + h4.y * wc4.y + h4.z * wc4.z + h4.w * wc4.w;
    }
#pragma unroll
    for (int a = 0; a < 6; a++) out[row * 6 + a] = acc[a] + bas[a];
    out[24576 + row] = accv + bcs;
}

// ---------------------------------------------------------------------------
// Launch
// ---------------------------------------------------------------------------
extern "C" void kernel_launch(void* const* d_in, const int* in_sizes, int n_in,
                              void* d_out, int out_size) {
    const float* x    = (const float*)d_in[0];
    const float* done = (const float*)d_in[1];
    const float* h0   = (const float*)d_in[2];
    const float* c0   = (const float*)d_in[3];
    const float* W1   = (const float*)d_in[4];
    const float* b1   = (const float*)d_in[5];
    const float* W2   = (const float*)d_in[6];
    const float* b2   = (const float*)d_in[7];
    const float* W3   = (const float*)d_in[8];
    const float* b3   = (const float*)d_in[9];
    const float* Wfc  = (const float*)d_in[10];
    const float* bfc  = (const float*)d_in[11];
    const float* W_ih = (const float*)d_in[12];
    const float* W_hh = (const float*)d_in[13];
    const float* b_ih = (const float*)d_in[14];
    const float* b_hh = (const float*)d_in[15];
    const float* Wa   = (const float*)d_in[16];
    const float* ba   = (const float*)d_in[17];
    const float* Wc   = (const float*)d_in[18];
    const float* bc   = (const float*)d_in[19];
    float* out = (float*)d_out;

    whh_transpose_kernel<<<128, 512>>>(W_hh);
    w1t_kernel<<<8, 256>>>(W1);
    w2t_kernel<<<128, 256>>>(W2);
    w3t_kernel<<<144, 256>>>(W3);
    conv1_gemm_kernel<<<12800, 256>>>(x, b1);
    conv2_gemm_kernel<<<5184, 256>>>(b2);
    conv3_gemm_kernel<<<3136, 256>>>(b3);
    fc_gemm_kernel<<<dim3(8, 64), 256>>>(Wfc, bfc);
    gates_gemm_kernel<<<dim3(8, 64), 256>>>(W_ih, b_ih, b_hh);
    lstm_kernel<<<BATCH, 512>>>(done, h0, c0, out);
    heads_kernel<<<16, 256>>>(Wa, ba, Wc, bc, out);
}

// round 9
// speedup vs baseline: 3.3970x; 1.1984x over previous
#include <cuda_runtime.h>
#include <mma.h>
#include <cstdint>

using namespace nvcuda;

#define NIMG   4096
#define TSTEPS 128
#define BATCH  32
#define HID    128

// Scratch (device globals; no allocation allowed)
__device__ float g_z1[(size_t)NIMG * 4 * 400 * 8];    // conv1 out [n][c=ic/8][pix400][ic%8]
__device__ float g_z2[(size_t)NIMG * 4 * 81 * 16];    // conv2 out [n][cc=oc/16][pix81][oc%16]
__device__ float g_z3[(size_t)NIMG * 3136];           // conv3 out, NCHW flatten
__device__ float g_hidden[(size_t)NIMG * 512];        // FC out
__device__ float g_gates[(size_t)NIMG * 512];         // x-proj of gates (+both biases)
__device__ float g_hs[(size_t)NIMG * HID];            // per-step hidden outputs
__device__ float g_whhT[HID * 512];                   // W_hh transposed
__device__ float g_w1t[64 * 32];                      // W1/255 in [k][oc]
__device__ float g_w2t[512 * 64];                     // W2 in [k][oc]
__device__ float g_w3t[576 * 64];                     // W3 in [k][oc]

// ---------------------------------------------------------------------------
// Weight re-layout preps
// ---------------------------------------------------------------------------
__global__ __launch_bounds__(256) void w1t_kernel(const float* __restrict__ W1) {
    const int id = blockIdx.x * 256 + threadIdx.x;   // 0..2047
    const int k = id >> 5, oc = id & 31;
    g_w1t[k * 32 + oc] = W1[oc * 64 + k] * (1.0f / 255.0f);
}
__global__ __launch_bounds__(256) void w2t_kernel(const float* __restrict__ W2) {
    const int id = blockIdx.x * 256 + threadIdx.x;   // 0..32767
    const int k = id >> 6, oc = id & 63;
    const int c = k >> 7, k16 = (k & 127) >> 3, icl = k & 7;
    g_w2t[k * 64 + oc] = W2[oc * 512 + (c * 8 + icl) * 16 + k16];
}
__global__ __launch_bounds__(256) void w3t_kernel(const float* __restrict__ W3) {
    const int id = blockIdx.x * 256 + threadIdx.x;   // 0..36863
    const int k = id >> 6, oc = id & 63;
    const int icc = k / 144, rem = k % 144, k9 = rem >> 4, icl = rem & 15;
    g_w3t[k * 64 + oc] = W3[oc * 576 + (icc * 16 + icl) * 9 + k9];
}
__global__ __launch_bounds__(512) void whh_transpose_kernel(const float* __restrict__ W_hh) {
    const int id = blockIdx.x * 512 + threadIdx.x;   // 0..65535
    const int k = id >> 9, j = id & 511;
    g_whhT[k * 512 + j] = W_hh[j * 128 + k];
}

// ---------------------------------------------------------------------------
// conv1 as implicit fp32 GEMM (r8 proven): M=1638400, N=32, K=64.
// ---------------------------------------------------------------------------
__global__ __launch_bounds__(256) void conv1_gemm_kernel(const float* __restrict__ x,
                                                         const float* __restrict__ b1) {
    __shared__ float As[16 * 132];
    __shared__ float Bs[16 * 36];
    const int tid = threadIdx.x;
    const int m0 = blockIdx.x * 128;
    const int ar = tid >> 1, q = tid & 1;
    const int m = m0 + ar;
    const int an = m / 400, ap = m % 400;
    const int iy = (ap / 20) * 4, ix = (ap % 20) * 4;
    const float* xrow = x + (size_t)an * 7056 + ix;
    const int kb = tid >> 3, ob = (tid & 7) << 2;
    const int tx = tid & 7, ty = tid >> 3;

    float acc[4][4];
#pragma unroll
    for (int i = 0; i < 4; i++)
#pragma unroll
        for (int j = 0; j < 4; j++) acc[i][j] = 0.f;

    for (int k0 = 0; k0 < 64; k0 += 16) {
        const int ky = (k0 >> 3) + q;
        const float* xp = xrow + (iy + ky) * 84;
        const float4 v0 = *(const float4*)(xp);
        const float4 v1 = *(const float4*)(xp + 4);
        float4 bvec;
        if (tid < 128) bvec = *(const float4*)&g_w1t[(k0 + kb) * 32 + ob];
        __syncthreads();
        const int kkb = q * 8;
        As[(kkb + 0) * 132 + ar] = v0.x;
        As[(kkb + 1) * 132 + ar] = v0.y;
        As[(kkb + 2) * 132 + ar] = v0.z;
        As[(kkb + 3) * 132 + ar] = v0.w;
        As[(kkb + 4) * 132 + ar] = v1.x;
        As[(kkb + 5) * 132 + ar] = v1.y;
        As[(kkb + 6) * 132 + ar] = v1.z;
        As[(kkb + 7) * 132 + ar] = v1.w;
        if (tid < 128) *(float4*)&Bs[kb * 36 + ob] = bvec;
        __syncthreads();
#pragma unroll
        for (int kk = 0; kk < 16; kk++) {
            const float4 a = *(const float4*)&As[kk * 132 + (ty << 2)];
            const float4 b = *(const float4*)&Bs[kk * 36 + (tx << 2)];
            acc[0][0] += a.x * b.x; acc[0][1] += a.x * b.y;
            acc[0][2] += a.x * b.z; acc[0][3] += a.x * b.w;
            acc[1][0] += a.y * b.x; acc[1][1] += a.y * b.y;
            acc[1][2] += a.y * b.z; acc[1][3] += a.y * b.w;
            acc[2][0] += a.z * b.x; acc[2][1] += a.z * b.y;
            acc[2][2] += a.z * b.z; acc[2][3] += a.z * b.w;
            acc[3][0] += a.w * b.x; acc[3][1] += a.w * b.y;
            acc[3][2] += a.w * b.z; acc[3][3] += a.w * b.w;
        }
    }

    const int oc0 = tx << 2;
    const int g = oc0 >> 3, l = oc0 & 7;
    const float4 bb = *(const float4*)&b1[oc0];
#pragma unroll
    for (int i = 0; i < 4; i++) {
        const int mm = m0 + (ty << 2) + i;
        const int n = mm / 400, p = mm % 400;
        float4 o;
        o.x = fmaxf(acc[i][0] + bb.x, 0.f);
        o.y = fmaxf(acc[i][1] + bb.y, 0.f);
        o.z = fmaxf(acc[i][2] + bb.z, 0.f);
        o.w = fmaxf(acc[i][3] + bb.w, 0.f);
        *(float4*)&g_z1[((size_t)n * 4 + g) * 3200 + p * 8 + l] = o;
    }
}

// ---------------------------------------------------------------------------
// TF32 WMMA common pieces. Block tile 128x64, BK=16, 256 threads (8 warps 4x2).
// smem: [0,2176) As0, [2176,4352) As1, [4352,5504) Bs0, [5504,6656) Bs1.
// Epilogue reuses smem as C stage [128][72].
// ---------------------------------------------------------------------------
#define LDA 136
#define LDB 72
#define LDC 72

typedef wmma::fragment<wmma::accumulator, 16, 16, 8, float> AccFrag;

__device__ __forceinline__ void mma_chunk(const float* __restrict__ As,
                                          const float* __restrict__ Bs,
                                          AccFrag (&acc)[2][2], int wm, int wn) {
#pragma unroll
    for (int ks = 0; ks < 16; ks += 8) {
        wmma::fragment<wmma::matrix_a, 16, 16, 8, wmma::precision::tf32, wmma::col_major> a[2];
        wmma::fragment<wmma::matrix_b, 16, 16, 8, wmma::precision::tf32, wmma::row_major> b[2];
#pragma unroll
        for (int i = 0; i < 2; i++) {
            wmma::load_matrix_sync(a[i], As + ks * LDA + wm * 32 + i * 16, LDA);
#pragma unroll
            for (int e = 0; e < a[i].num_elements; e++)
                a[i].x[e] = wmma::__float_to_tf32(a[i].x[e]);
        }
#pragma unroll
        for (int j = 0; j < 2; j++) {
            wmma::load_matrix_sync(b[j], Bs + ks * LDB + wn * 32 + j * 16, LDB);
#pragma unroll
            for (int e = 0; e < b[j].num_elements; e++)
                b[j].x[e] = wmma::__float_to_tf32(b[j].x[e]);
        }
#pragma unroll
        for (int i = 0; i < 2; i++)
#pragma unroll
            for (int j = 0; j < 2; j++)
                wmma::mma_sync(acc[i][j], a[i], b[j], acc[i][j]);
    }
}

#define STAGE_A8(dst, ar, q, v0, v1)                       \
    {                                                      \
        const int _kb = (q) * 8;                           \
        (dst)[(_kb + 0) * LDA + (ar)] = v0.x;              \
        (dst)[(_kb + 1) * LDA + (ar)] = v0.y;              \
        (dst)[(_kb + 2) * LDA + (ar)] = v0.z;              \
        (dst)[(_kb + 3) * LDA + (ar)] = v0.w;              \
        (dst)[(_kb + 4) * LDA + (ar)] = v1.x;              \
        (dst)[(_kb + 5) * LDA + (ar)] = v1.y;              \
        (dst)[(_kb + 6) * LDA + (ar)] = v1.z;              \
        (dst)[(_kb + 7) * LDA + (ar)] = v1.w;              \
    }

__device__ __forceinline__ void store_c_frags(float* smem, AccFrag (&acc)[2][2],
                                              int wm, int wn) {
#pragma unroll
    for (int i = 0; i < 2; i++)
#pragma unroll
        for (int j = 0; j < 2; j++)
            wmma::store_matrix_sync(&smem[(wm * 32 + i * 16) * LDC + wn * 32 + j * 16],
                                    acc[i][j], LDC, wmma::mem_row_major);
}

// ---------------------------------------------------------------------------
// conv2 TF32: M=331776 (=(n,p)), K=512, N=64.
// ---------------------------------------------------------------------------
__global__ __launch_bounds__(256) void conv2_wmma_kernel(const float* __restrict__ b2) {
    __shared__ float smem[9216];
    const int tid = threadIdx.x;
    const int wid = tid >> 5, wm = wid >> 1, wn = wid & 1;
    const int m0 = blockIdx.x * 128;
    const int ar = tid >> 1, q = tid & 1;
    const int m = m0 + ar;
    const int an = m / 81, ap = m % 81;
    const int aiy = (ap / 9) * 2, aix = (ap % 9) * 2;
    const int kb = tid >> 4, ob = (tid & 15) << 2;

    AccFrag acc[2][2];
#pragma unroll
    for (int i = 0; i < 2; i++)
#pragma unroll
        for (int j = 0; j < 2; j++) wmma::fill_fragment(acc[i][j], 0.f);

    float* As = smem;
    float* Bs = smem + 4352;

#define C2_LOADA(k0, v0, v1)                                                     \
    {                                                                            \
        const int g = ((k0) >> 3) + q;                                           \
        const int c = g >> 4, k16 = g & 15;                                      \
        const int ky = k16 >> 2, kx = k16 & 3;                                   \
        const float* p = &g_z1[(((size_t)an * 4 + c) * 400 +                     \
                                (aiy + ky) * 20 + aix + kx) * 8];                \
        v0 = *(const float4*)p; v1 = *(const float4*)(p + 4);                    \
    }

    {
        float4 a0, a1;
        C2_LOADA(0, a0, a1);
        const float4 bv = *(const float4*)&g_w2t[(size_t)kb * 64 + ob];
        STAGE_A8(As, ar, q, a0, a1);
        *(float4*)&Bs[kb * LDB + ob] = bv;
    }
    __syncthreads();

    int buf = 0;
    for (int k0 = 16; k0 < 512; k0 += 16) {
        float4 a0, a1;
        C2_LOADA(k0, a0, a1);
        const float4 bv = *(const float4*)&g_w2t[(size_t)(k0 + kb) * 64 + ob];
        mma_chunk(As + buf * 2176, Bs + buf * 1152, acc, wm, wn);
        float* An = As + (buf ^ 1) * 2176;
        float* Bn = Bs + (buf ^ 1) * 1152;
        STAGE_A8(An, ar, q, a0, a1);
        *(float4*)&Bn[kb * LDB + ob] = bv;
        __syncthreads();
        buf ^= 1;
    }
    mma_chunk(As + buf * 2176, Bs + buf * 1152, acc, wm, wn);
    __syncthreads();
    store_c_frags(smem, acc, wm, wn);
    __syncthreads();

    const int r = tid >> 1, h = tid & 1;
    const int rn = (m0 + r) / 81, rp = (m0 + r) % 81;
#pragma unroll
    for (int j = 0; j < 8; j++) {
        const int oc = h * 32 + j * 4;
        float4 v = *(float4*)&smem[r * LDC + oc];
        const float4 bb = *(const float4*)&b2[oc];
        v.x = fmaxf(v.x + bb.x, 0.f);
        v.y = fmaxf(v.y + bb.y, 0.f);
        v.z = fmaxf(v.z + bb.z, 0.f);
        v.w = fmaxf(v.w + bb.w, 0.f);
        *(float4*)&g_z2[(((size_t)rn * 4 + (oc >> 4)) * 81 + rp) * 16 + (oc & 15)] = v;
    }
}

// ---------------------------------------------------------------------------
// conv3 TF32: M=200704 (=(n,p)), K=576, N=64.
// ---------------------------------------------------------------------------
__global__ __launch_bounds__(256) void conv3_wmma_kernel(const float* __restrict__ b3) {
    __shared__ float smem[9216];
    const int tid = threadIdx.x;
    const int wid = tid >> 5, wm = wid >> 1, wn = wid & 1;
    const int m0 = blockIdx.x * 128;
    const int ar = tid >> 1, q = tid & 1;
    const int m = m0 + ar;
    const int an = m / 49, ap = m % 49;
    const int aoy = ap / 7, aox = ap % 7;
    const int kb = tid >> 4, ob = (tid & 15) << 2;

    AccFrag acc[2][2];
#pragma unroll
    for (int i = 0; i < 2; i++)
#pragma unroll
        for (int j = 0; j < 2; j++) wmma::fill_fragment(acc[i][j], 0.f);

    float* As = smem;
    float* Bs = smem + 4352;

#define C3_LOADA(k0, v0, v1)                                                     \
    {                                                                            \
        const int g = (k0) >> 4;                                                 \
        const int icc = g / 9, k9 = g % 9;                                       \
        const int ky = k9 / 3, kx = k9 % 3;                                      \
        const float* p = &g_z2[(((size_t)an * 4 + icc) * 81 +                    \
                                (aoy + ky) * 9 + aox + kx) * 16 + q * 8];        \
        v0 = *(const float4*)p; v1 = *(const float4*)(p + 4);                    \
    }

    {
        float4 a0, a1;
        C3_LOADA(0, a0, a1);
        const float4 bv = *(const float4*)&g_w3t[(size_t)kb * 64 + ob];
        STAGE_A8(As, ar, q, a0, a1);
        *(float4*)&Bs[kb * LDB + ob] = bv;
    }
    __syncthreads();

    int buf = 0;
    for (int k0 = 16; k0 < 576; k0 += 16) {
        float4 a0, a1;
        C3_LOADA(k0, a0, a1);
        const float4 bv = *(const float4*)&g_w3t[(size_t)(k0 + kb) * 64 + ob];
        mma_chunk(As + buf * 2176, Bs + buf * 1152, acc, wm, wn);
        float* An = As + (buf ^ 1) * 2176;
        float* Bn = Bs + (buf ^ 1) * 1152;
        STAGE_A8(An, ar, q, a0, a1);
        *(float4*)&Bn[kb * LDB + ob] = bv;
        __syncthreads();
        buf ^= 1;
    }
    mma_chunk(As + buf * 2176, Bs + buf * 1152, acc, wm, wn);
    __syncthreads();
    store_c_frags(smem, acc, wm, wn);
    __syncthreads();

    const int r = tid >> 1, h = tid & 1;
    const int rn = (m0 + r) / 49, rp = (m0 + r) % 49;
#pragma unroll
    for (int j = 0; j < 8; j++) {
        const int oc = h * 32 + j * 4;
        const float4 v = *(float4*)&smem[r * LDC + oc];
        const float4 bb = *(const float4*)&b3[oc];
        float* zp = &g_z3[(size_t)rn * 3136 + oc * 49 + rp];
        zp[0]   = fmaxf(v.x + bb.x, 0.f);
        zp[49]  = fmaxf(v.y + bb.y, 0.f);
        zp[98]  = fmaxf(v.z + bb.z, 0.f);
        zp[147] = fmaxf(v.w + bb.w, 0.f);
    }
}

// ---------------------------------------------------------------------------
// Dense TF32 GEMM (fc / gates): C[M,512-slice] = A[M,K] B[N,K]^T + biases.
// ---------------------------------------------------------------------------
__device__ __forceinline__ void gemm_wmma(const float* __restrict__ A,
                                          const float* __restrict__ B,
                                          float* __restrict__ C, int K,
                                          const float* __restrict__ bias1,
                                          const float* __restrict__ bias2,
                                          bool relu) {
    __shared__ float smem[9216];
    const int tid = threadIdx.x;
    const int wid = tid >> 5, wm = wid >> 1, wn = wid & 1;
    const int m0 = blockIdx.y * 128, n0 = blockIdx.x * 64;
    const int ar = tid >> 1, q = tid & 1;
    const int bn = tid >> 2, bq = tid & 3;
    const float* Ap = A + (size_t)(m0 + ar) * K + q * 8;
    const float* Bp = B + (size_t)(n0 + bn) * K + bq * 4;

    AccFrag acc[2][2];
#pragma unroll
    for (int i = 0; i < 2; i++)
#pragma unroll
        for (int j = 0; j < 2; j++) wmma::fill_fragment(acc[i][j], 0.f);

    float* As = smem;
    float* Bs = smem + 4352;

    {
        const float4 a0 = *(const float4*)(Ap);
        const float4 a1 = *(const float4*)(Ap + 4);
        const float4 bv = *(const float4*)(Bp);
        STAGE_A8(As, ar, q, a0, a1);
        Bs[(bq * 4 + 0) * LDB + bn] = bv.x;
        Bs[(bq * 4 + 1) * LDB + bn] = bv.y;
        Bs[(bq * 4 + 2) * LDB + bn] = bv.z;
        Bs[(bq * 4 + 3) * LDB + bn] = bv.w;
    }
    __syncthreads();

    int buf = 0;
    for (int k0 = 16; k0 < K; k0 += 16) {
        const float4 a0 = *(const float4*)(Ap + k0);
        const float4 a1 = *(const float4*)(Ap + k0 + 4);
        const float4 bv = *(const float4*)(Bp + k0);
        mma_chunk(As + buf * 2176, Bs + buf * 1152, acc, wm, wn);
        float* An = As + (buf ^ 1) * 2176;
        float* Bn = Bs + (buf ^ 1) * 1152;
        STAGE_A8(An, ar, q, a0, a1);
        Bn[(bq * 4 + 0) * LDB + bn] = bv.x;
        Bn[(bq * 4 + 1) * LDB + bn] = bv.y;
        Bn[(bq * 4 + 2) * LDB + bn] = bv.z;
        Bn[(bq * 4 + 3) * LDB + bn] = bv.w;
        __syncthreads();
        buf ^= 1;
    }
    mma_chunk(As + buf * 2176, Bs + buf * 1152, acc, wm, wn);
    __syncthreads();
    store_c_frags(smem, acc, wm, wn);
    __syncthreads();

    const int r = tid >> 1, h = tid & 1;
#pragma unroll
    for (int j = 0; j < 8; j++) {
        const int c = h * 32 + j * 4;
        float4 v = *(float4*)&smem[r * LDC + c];
        float b0 = bias1[n0 + c + 0] + (bias2 ? bias2[n0 + c + 0] : 0.f);
        float b1v = bias1[n0 + c + 1] + (bias2 ? bias2[n0 + c + 1] : 0.f);
        float b2v = bias1[n0 + c + 2] + (bias2 ? bias2[n0 + c + 2] : 0.f);
        float b3v = bias1[n0 + c + 3] + (bias2 ? bias2[n0 + c + 3] : 0.f);
        v.x += b0; v.y += b1v; v.z += b2v; v.w += b3v;
        if (relu) {
            v.x = fmaxf(v.x, 0.f); v.y = fmaxf(v.y, 0.f);
            v.z = fmaxf(v.z, 0.f); v.w = fmaxf(v.w, 0.f);
        }
        *(float4*)&C[(size_t)(m0 + r) * 512 + n0 + c] = v;
    }
}

__global__ __launch_bounds__(256) void fc_gemm_kernel(const float* __restrict__ Wfc,
                                                      const float* __restrict__ bfc) {
    gemm_wmma(g_z3, Wfc, g_hidden, 3136, bfc, nullptr, true);
}
__global__ __launch_bounds__(256) void gates_gemm_kernel(const float* __restrict__ W_ih,
                                                         const float* __restrict__ b_ih,
                                                         const float* __restrict__ b_hh) {
    gemm_wmma(g_hidden, W_ih, g_gates, 512, b_ih, b_hh, false);
}

// ---------------------------------------------------------------------------
// LSTM: one block per batch element, 512 threads (proven coalesced, fp32).
// ---------------------------------------------------------------------------
__device__ __forceinline__ float sigmoidf_(float v) {
    return 1.0f / (1.0f + __expf(-v));
}

__global__ __launch_bounds__(512) void lstm_kernel(const float* __restrict__ done,
                                                   const float* __restrict__ h0,
                                                   const float* __restrict__ c0,
                                                   float* __restrict__ out) {
    __shared__ float hm[HID];
    __shared__ float cs[HID];
    __shared__ float hs[HID];
    __shared__ float part[4 * 512];
    const int b = blockIdx.x;
    const int tid = threadIdx.x;
    const int j4 = tid & 127;
    const int ks = tid >> 7;

    if (tid < HID) {
        hs[tid] = h0[b * HID + tid];
        cs[tid] = c0[b * HID + tid];
    }
    __syncthreads();

    for (int t = 0; t < TSTEPS; t++) {
        const float mask = 1.0f - done[t * BATCH + b];
        if (tid < HID) hm[tid] = hs[tid] * mask;
        __syncthreads();

        float a0 = 0.f, a1 = 0.f, a2 = 0.f, a3 = 0.f;
        const float4* __restrict__ wt = (const float4*)&g_whhT[(ks * 32) * 512] + j4;
        const float* __restrict__ hk = &hm[ks * 32];
#pragma unroll
        for (int kk = 0; kk < 32; kk++) {
            const float4 w = wt[kk * 128];
            const float h = hk[kk];
            a0 += w.x * h; a1 += w.y * h; a2 += w.z * h; a3 += w.w * h;
        }
        float4 pv = {a0, a1, a2, a3};
        *(float4*)&part[ks * 512 + j4 * 4] = pv;
        __syncthreads();

        const float gx = g_gates[(size_t)(t * BATCH + b) * 512 + tid];
        const float gsum = part[tid] + part[512 + tid] + part[1024 + tid] +
                           part[1536 + tid] + gx;
        part[tid] = gsum;
        __syncthreads();

        if (tid < HID) {
            const float gi = part[tid];
            const float gf = part[tid + 128];
            const float gc = part[tid + 256];
            const float go = part[tid + 384];
            float c = cs[tid] * mask;
            c = sigmoidf_(gf) * c + sigmoidf_(gi) * tanhf(gc);
            const float h = sigmoidf_(go) * tanhf(c);
            cs[tid] = c;
            hs[tid] = h;
            g_hs[(size_t)(t * BATCH + b) * HID + tid] = h;
            if (t == TSTEPS - 1) {
                out[28672 + b * HID + tid] = h;
                out[32768 + b * HID + tid] = c;
            }
        }
        __syncthreads();
    }
}

// ---------------------------------------------------------------------------
// Heads: logits (4096x6) and value (4096x1) from g_hs.
// ---------------------------------------------------------------------------
__global__ __launch_bounds__(256) void heads_kernel(const float* __restrict__ Wa,
                                                    const float* __restrict__ ba,
                                                    const float* __restrict__ Wc,
                                                    const float* __restrict__ bc,
                                                    float* __restrict__ out) {
    __shared__ float was[6 * 128];
    __shared__ float wcs[128];
    __shared__ float bas[6];
    __shared__ float bcs;
    const int tid = threadIdx.x;
    for (int i = tid; i < 768; i += 256) was[i] = Wa[i];
    if (tid < 128) wcs[tid] = Wc[tid];
    if (tid < 6) bas[tid] = ba[tid];
    if (tid == 0) bcs = bc[0];
    __syncthreads();

    const int row = blockIdx.x * 256 + tid;
    const float* hp = &g_hs[(size_t)row * 128];
    float acc[6] = {0.f, 0.f, 0.f, 0.f, 0.f, 0.f};
    float accv = 0.f;
    for (int k = 0; k < 128; k += 4) {
        const float4 h4 = *(const float4*)&hp[k];
#pragma unroll
        for (int a = 0; a < 6; a++) {
            const float4 w4 = *(const float4*)&was[a * 128 + k];
            acc[a] += h4.x * w4.x + h4.y * w4.y + h4.z * w4.z + h4.w * w4.w;
        }
        const float4 wc4 = *(const float4*)&wcs[k];
        accv += h4.x * wc4.x + h4.y * wc4.y + h4.z * wc4.z + h4.w * wc4.w;
    }
#pragma unroll
    for (int a = 0; a < 6; a++) out[row * 6 + a] = acc[a] + bas[a];
    out[24576 + row] = accv + bcs;
}

// ---------------------------------------------------------------------------
// Launch
// ---------------------------------------------------------------------------
extern "C" void kernel_launch(void* const* d_in, const int* in_sizes, int n_in,
                              void* d_out, int out_size) {
    const float* x    = (const float*)d_in[0];
    const float* done = (const float*)d_in[1];
    const float* h0   = (const float*)d_in[2];
    const float* c0   = (const float*)d_in[3];
    const float* W1   = (const float*)d_in[4];
    const float* b1   = (const float*)d_in[5];
    const float* W2   = (const float*)d_in[6];
    const float* b2   = (const float*)d_in[7];
    const float* W3   = (const float*)d_in[8];
    const float* b3   = (const float*)d_in[9];
    const float* Wfc  = (const float*)d_in[10];
    const float* bfc  = (const float*)d_in[11];
    const float* W_ih = (const float*)d_in[12];
    const float* W_hh = (const float*)d_in[13];
    const float* b_ih = (const float*)d_in[14];
    const float* b_hh = (const float*)d_in[15];
    const float* Wa   = (const float*)d_in[16];
    const float* ba   = (const float*)d_in[17];
    const float* Wc   = (const float*)d_in[18];
    const float* bc   = (const float*)d_in[19];
    float* out = (float*)d_out;

    whh_transpose_kernel<<<128, 512>>>(W_hh);
    w1t_kernel<<<8, 256>>>(W1);
    w2t_kernel<<<128, 256>>>(W2);
    w3t_kernel<<<144, 256>>>(W3);
    conv1_gemm_kernel<<<12800, 256>>>(x, b1);
    conv2_wmma_kernel<<<2592, 256>>>(b2);
    conv3_wmma_kernel<<<1568, 256>>>(b3);
    fc_gemm_kernel<<<dim3(8, 32), 256>>>(Wfc, bfc);
    gates_gemm_kernel<<<dim3(8, 32), 256>>>(W_ih, b_ih, b_hh);
    lstm_kernel<<<BATCH, 512>>>(done, h0, c0, out);
    heads_kernel<<<16, 256>>>(Wa, ba, Wc, bc, out);
}

// round 10
// speedup vs baseline: 3.6319x; 1.0691x over previous
#include <cuda_runtime.h>
#include <mma.h>
#include <cstdint>

using namespace nvcuda;

#define NIMG   4096
#define TSTEPS 128
#define BATCH  32
#define HID    128

// Scratch (device globals; no allocation allowed)
__device__ float g_z1[(size_t)NIMG * 4 * 400 * 8];    // conv1 out [n][c=ic/8][pix400][ic%8]
__device__ float g_z2[(size_t)NIMG * 4 * 81 * 16];    // conv2 out [n][cc=oc/16][pix81][oc%16]
__device__ float g_z3[(size_t)NIMG * 3136];           // conv3 out, NCHW flatten
__device__ float g_hidden[(size_t)NIMG * 512];        // FC out
__device__ float g_gates[(size_t)NIMG * 512];         // x-proj of gates (+both biases)
__device__ float g_hs[(size_t)NIMG * HID];            // per-step hidden outputs
__device__ float g_whhT[HID * 512];                   // W_hh transposed
__device__ float g_w1t[64 * 32];                      // W1/255 in [k][oc]
__device__ float g_w2t[512 * 64];                     // W2 in [k][oc]  (tf32-rounded)
__device__ float g_w3t[576 * 64];                     // W3 in [k][oc]  (tf32-rounded)

// ---------------------------------------------------------------------------
// Weight re-layout preps (conv weights stored pre-rounded to tf32)
// ---------------------------------------------------------------------------
__global__ __launch_bounds__(256) void w1t_kernel(const float* __restrict__ W1) {
    const int id = blockIdx.x * 256 + threadIdx.x;   // 0..2047
    const int k = id >> 5, oc = id & 31;
    g_w1t[k * 32 + oc] = W1[oc * 64 + k] * (1.0f / 255.0f);
}
__global__ __launch_bounds__(256) void w2t_kernel(const float* __restrict__ W2) {
    const int id = blockIdx.x * 256 + threadIdx.x;   // 0..32767
    const int k = id >> 6, oc = id & 63;
    const int c = k >> 7, k16 = (k & 127) >> 3, icl = k & 7;
    g_w2t[k * 64 + oc] = wmma::__float_to_tf32(W2[oc * 512 + (c * 8 + icl) * 16 + k16]);
}
__global__ __launch_bounds__(256) void w3t_kernel(const float* __restrict__ W3) {
    const int id = blockIdx.x * 256 + threadIdx.x;   // 0..36863
    const int k = id >> 6, oc = id & 63;
    const int icc = k / 144, rem = k % 144, k9 = rem >> 4, icl = rem & 15;
    g_w3t[k * 64 + oc] = wmma::__float_to_tf32(W3[oc * 576 + (icc * 16 + icl) * 9 + k9]);
}
__global__ __launch_bounds__(512) void whh_transpose_kernel(const float* __restrict__ W_hh) {
    const int id = blockIdx.x * 512 + threadIdx.x;   // 0..65535
    const int k = id >> 9, j = id & 511;
    g_whhT[k * 512 + j] = W_hh[j * 128 + k];
}

// ---------------------------------------------------------------------------
// conv1 as implicit fp32 GEMM (r8 proven): M=1638400, N=32, K=64.
// ---------------------------------------------------------------------------
__global__ __launch_bounds__(256) void conv1_gemm_kernel(const float* __restrict__ x,
                                                         const float* __restrict__ b1) {
    __shared__ float As[16 * 132];
    __shared__ float Bs[16 * 36];
    const int tid = threadIdx.x;
    const int m0 = blockIdx.x * 128;
    const int ar = tid >> 1, q = tid & 1;
    const int m = m0 + ar;
    const int an = m / 400, ap = m % 400;
    const int iy = (ap / 20) * 4, ix = (ap % 20) * 4;
    const float* xrow = x + (size_t)an * 7056 + ix;
    const int kb = tid >> 3, ob = (tid & 7) << 2;
    const int tx = tid & 7, ty = tid >> 3;

    float acc[4][4];
#pragma unroll
    for (int i = 0; i < 4; i++)
#pragma unroll
        for (int j = 0; j < 4; j++) acc[i][j] = 0.f;

    for (int k0 = 0; k0 < 64; k0 += 16) {
        const int ky = (k0 >> 3) + q;
        const float* xp = xrow + (iy + ky) * 84;
        const float4 v0 = *(const float4*)(xp);
        const float4 v1 = *(const float4*)(xp + 4);
        float4 bvec;
        if (tid < 128) bvec = *(const float4*)&g_w1t[(k0 + kb) * 32 + ob];
        __syncthreads();
        const int kkb = q * 8;
        As[(kkb + 0) * 132 + ar] = v0.x;
        As[(kkb + 1) * 132 + ar] = v0.y;
        As[(kkb + 2) * 132 + ar] = v0.z;
        As[(kkb + 3) * 132 + ar] = v0.w;
        As[(kkb + 4) * 132 + ar] = v1.x;
        As[(kkb + 5) * 132 + ar] = v1.y;
        As[(kkb + 6) * 132 + ar] = v1.z;
        As[(kkb + 7) * 132 + ar] = v1.w;
        if (tid < 128) *(float4*)&Bs[kb * 36 + ob] = bvec;
        __syncthreads();
#pragma unroll
        for (int kk = 0; kk < 16; kk++) {
            const float4 a = *(const float4*)&As[kk * 132 + (ty << 2)];
            const float4 b = *(const float4*)&Bs[kk * 36 + (tx << 2)];
            acc[0][0] += a.x * b.x; acc[0][1] += a.x * b.y;
            acc[0][2] += a.x * b.z; acc[0][3] += a.x * b.w;
            acc[1][0] += a.y * b.x; acc[1][1] += a.y * b.y;
            acc[1][2] += a.y * b.z; acc[1][3] += a.y * b.w;
            acc[2][0] += a.z * b.x; acc[2][1] += a.z * b.y;
            acc[2][2] += a.z * b.z; acc[2][3] += a.z * b.w;
            acc[3][0] += a.w * b.x; acc[3][1] += a.w * b.y;
            acc[3][2] += a.w * b.z; acc[3][3] += a.w * b.w;
        }
    }

    const int oc0 = tx << 2;
    const int g = oc0 >> 3, l = oc0 & 7;
    const float4 bb = *(const float4*)&b1[oc0];
#pragma unroll
    for (int i = 0; i < 4; i++) {
        const int mm = m0 + (ty << 2) + i;
        const int n = mm / 400, p = mm % 400;
        float4 o;
        o.x = fmaxf(acc[i][0] + bb.x, 0.f);
        o.y = fmaxf(acc[i][1] + bb.y, 0.f);
        o.z = fmaxf(acc[i][2] + bb.z, 0.f);
        o.w = fmaxf(acc[i][3] + bb.w, 0.f);
        *(float4*)&g_z1[((size_t)n * 4 + g) * 3200 + p * 8 + l] = o;
    }
}

// ---------------------------------------------------------------------------
// TF32 WMMA common pieces. Block tile 128x64, BK=16, 256 threads (8 warps 4x2).
// smem values are pre-rounded to tf32 at staging -> NO fragment conversion.
// ---------------------------------------------------------------------------
#define LDA 136
#define LDB 72
#define LDC 72

typedef wmma::fragment<wmma::accumulator, 16, 16, 8, float> AccFrag;

__device__ __forceinline__ void mma_chunk(const float* __restrict__ As,
                                          const float* __restrict__ Bs,
                                          AccFrag (&acc)[2][2], int wm, int wn) {
#pragma unroll
    for (int ks = 0; ks < 16; ks += 8) {
        wmma::fragment<wmma::matrix_a, 16, 16, 8, wmma::precision::tf32, wmma::col_major> a[2];
        wmma::fragment<wmma::matrix_b, 16, 16, 8, wmma::precision::tf32, wmma::row_major> b[2];
#pragma unroll
        for (int i = 0; i < 2; i++)
            wmma::load_matrix_sync(a[i], As + ks * LDA + wm * 32 + i * 16, LDA);
#pragma unroll
        for (int j = 0; j < 2; j++)
            wmma::load_matrix_sync(b[j], Bs + ks * LDB + wn * 32 + j * 16, LDB);
#pragma unroll
        for (int i = 0; i < 2; i++)
#pragma unroll
            for (int j = 0; j < 2; j++)
                wmma::mma_sync(acc[i][j], a[i], b[j], acc[i][j]);
    }
}

// stage 8 consecutive-k A values (tf32-rounded at store)
#define STAGE_A8(dst, ar, q, v0, v1)                                  \
    {                                                                 \
        const int _kb = (q) * 8;                                      \
        (dst)[(_kb + 0) * LDA + (ar)] = wmma::__float_to_tf32(v0.x);  \
        (dst)[(_kb + 1) * LDA + (ar)] = wmma::__float_to_tf32(v0.y);  \
        (dst)[(_kb + 2) * LDA + (ar)] = wmma::__float_to_tf32(v0.z);  \
        (dst)[(_kb + 3) * LDA + (ar)] = wmma::__float_to_tf32(v0.w);  \
        (dst)[(_kb + 4) * LDA + (ar)] = wmma::__float_to_tf32(v1.x);  \
        (dst)[(_kb + 5) * LDA + (ar)] = wmma::__float_to_tf32(v1.y);  \
        (dst)[(_kb + 6) * LDA + (ar)] = wmma::__float_to_tf32(v1.z);  \
        (dst)[(_kb + 7) * LDA + (ar)] = wmma::__float_to_tf32(v1.w);  \
    }

__device__ __forceinline__ void store_c_frags(float* smem, AccFrag (&acc)[2][2],
                                              int wm, int wn) {
#pragma unroll
    for (int i = 0; i < 2; i++)
#pragma unroll
        for (int j = 0; j < 2; j++)
            wmma::store_matrix_sync(&smem[(wm * 32 + i * 16) * LDC + wn * 32 + j * 16],
                                    acc[i][j], LDC, wmma::mem_row_major);
}

// ---------------------------------------------------------------------------
// conv2 TF32: M=331776 (=(n,p)), K=512, N=64.  (weights pre-rounded in g_w2t)
// ---------------------------------------------------------------------------
__global__ __launch_bounds__(256) void conv2_wmma_kernel(const float* __restrict__ b2) {
    __shared__ float smem[9216];
    const int tid = threadIdx.x;
    const int wid = tid >> 5, wm = wid >> 1, wn = wid & 1;
    const int m0 = blockIdx.x * 128;
    const int ar = tid >> 1, q = tid & 1;
    const int m = m0 + ar;
    const int an = m / 81, ap = m % 81;
    const int aiy = (ap / 9) * 2, aix = (ap % 9) * 2;
    const int kb = tid >> 4, ob = (tid & 15) << 2;

    AccFrag acc[2][2];
#pragma unroll
    for (int i = 0; i < 2; i++)
#pragma unroll
        for (int j = 0; j < 2; j++) wmma::fill_fragment(acc[i][j], 0.f);

    float* As = smem;
    float* Bs = smem + 4352;

#define C2_LOADA(k0, v0, v1)                                                     \
    {                                                                            \
        const int g = ((k0) >> 3) + q;                                           \
        const int c = g >> 4, k16 = g & 15;                                      \
        const int ky = k16 >> 2, kx = k16 & 3;                                   \
        const float* p = &g_z1[(((size_t)an * 4 + c) * 400 +                     \
                                (aiy + ky) * 20 + aix + kx) * 8];                \
        v0 = *(const float4*)p; v1 = *(const float4*)(p + 4);                    \
    }

    {
        float4 a0, a1;
        C2_LOADA(0, a0, a1);
        const float4 bv = *(const float4*)&g_w2t[(size_t)kb * 64 + ob];
        STAGE_A8(As, ar, q, a0, a1);
        *(float4*)&Bs[kb * LDB + ob] = bv;
    }
    __syncthreads();

    int buf = 0;
    for (int k0 = 16; k0 < 512; k0 += 16) {
        float4 a0, a1;
        C2_LOADA(k0, a0, a1);
        const float4 bv = *(const float4*)&g_w2t[(size_t)(k0 + kb) * 64 + ob];
        mma_chunk(As + buf * 2176, Bs + buf * 1152, acc, wm, wn);
        float* An = As + (buf ^ 1) * 2176;
        float* Bn = Bs + (buf ^ 1) * 1152;
        STAGE_A8(An, ar, q, a0, a1);
        *(float4*)&Bn[kb * LDB + ob] = bv;
        __syncthreads();
        buf ^= 1;
    }
    mma_chunk(As + buf * 2176, Bs + buf * 1152, acc, wm, wn);
    __syncthreads();
    store_c_frags(smem, acc, wm, wn);
    __syncthreads();

    const int r = tid >> 1, h = tid & 1;
    const int rn = (m0 + r) / 81, rp = (m0 + r) % 81;
#pragma unroll
    for (int j = 0; j < 8; j++) {
        const int oc = h * 32 + j * 4;
        float4 v = *(float4*)&smem[r * LDC + oc];
        const float4 bb = *(const float4*)&b2[oc];
        v.x = fmaxf(v.x + bb.x, 0.f);
        v.y = fmaxf(v.y + bb.y, 0.f);
        v.z = fmaxf(v.z + bb.z, 0.f);
        v.w = fmaxf(v.w + bb.w, 0.f);
        *(float4*)&g_z2[(((size_t)rn * 4 + (oc >> 4)) * 81 + rp) * 16 + (oc & 15)] = v;
    }
}

// ---------------------------------------------------------------------------
// conv3 TF32: M=200704 (=(n,p)), K=576, N=64.  (weights pre-rounded in g_w3t)
// ---------------------------------------------------------------------------
__global__ __launch_bounds__(256) void conv3_wmma_kernel(const float* __restrict__ b3) {
    __shared__ float smem[9216];
    const int tid = threadIdx.x;
    const int wid = tid >> 5, wm = wid >> 1, wn = wid & 1;
    const int m0 = blockIdx.x * 128;
    const int ar = tid >> 1, q = tid & 1;
    const int m = m0 + ar;
    const int an = m / 49, ap = m % 49;
    const int aoy = ap / 7, aox = ap % 7;
    const int kb = tid >> 4, ob = (tid & 15) << 2;

    AccFrag acc[2][2];
#pragma unroll
    for (int i = 0; i < 2; i++)
#pragma unroll
        for (int j = 0; j < 2; j++) wmma::fill_fragment(acc[i][j], 0.f);

    float* As = smem;
    float* Bs = smem + 4352;

#define C3_LOADA(k0, v0, v1)                                                     \
    {                                                                            \
        const int g = (k0) >> 4;                                                 \
        const int icc = g / 9, k9 = g % 9;                                       \
        const int ky = k9 / 3, kx = k9 % 3;                                      \
        const float* p = &g_z2[(((size_t)an * 4 + icc) * 81 +                    \
                                (aoy + ky) * 9 + aox + kx) * 16 + q * 8];        \
        v0 = *(const float4*)p; v1 = *(const float4*)(p + 4);                    \
    }

    {
        float4 a0, a1;
        C3_LOADA(0, a0, a1);
        const float4 bv = *(const float4*)&g_w3t[(size_t)kb * 64 + ob];
        STAGE_A8(As, ar, q, a0, a1);
        *(float4*)&Bs[kb * LDB + ob] = bv;
    }
    __syncthreads();

    int buf = 0;
    for (int k0 = 16; k0 < 576; k0 += 16) {
        float4 a0, a1;
        C3_LOADA(k0, a0, a1);
        const float4 bv = *(const float4*)&g_w3t[(size_t)(k0 + kb) * 64 + ob];
        mma_chunk(As + buf * 2176, Bs + buf * 1152, acc, wm, wn);
        float* An = As + (buf ^ 1) * 2176;
        float* Bn = Bs + (buf ^ 1) * 1152;
        STAGE_A8(An, ar, q, a0, a1);
        *(float4*)&Bn[kb * LDB + ob] = bv;
        __syncthreads();
        buf ^= 1;
    }
    mma_chunk(As + buf * 2176, Bs + buf * 1152, acc, wm, wn);
    __syncthreads();
    store_c_frags(smem, acc, wm, wn);
    __syncthreads();

    const int r = tid >> 1, h = tid & 1;
    const int rn = (m0 + r) / 49, rp = (m0 + r) % 49;
#pragma unroll
    for (int j = 0; j < 8; j++) {
        const int oc = h * 32 + j * 4;
        const float4 v = *(float4*)&smem[r * LDC + oc];
        const float4 bb = *(const float4*)&b3[oc];
        float* zp = &g_z3[(size_t)rn * 3136 + oc * 49 + rp];
        zp[0]   = fmaxf(v.x + bb.x, 0.f);
        zp[49]  = fmaxf(v.y + bb.y, 0.f);
        zp[98]  = fmaxf(v.z + bb.z, 0.f);
        zp[147] = fmaxf(v.w + bb.w, 0.f);
    }
}

// ---------------------------------------------------------------------------
// Dense TF32 GEMM (fc / gates): tf32-rounded at staging for both A and B.
// ---------------------------------------------------------------------------
__device__ __forceinline__ void gemm_wmma(const float* __restrict__ A,
                                          const float* __restrict__ B,
                                          float* __restrict__ C, int K,
                                          const float* __restrict__ bias1,
                                          const float* __restrict__ bias2,
                                          bool relu) {
    __shared__ float smem[9216];
    const int tid = threadIdx.x;
    const int wid = tid >> 5, wm = wid >> 1, wn = wid & 1;
    const int m0 = blockIdx.y * 128, n0 = blockIdx.x * 64;
    const int ar = tid >> 1, q = tid & 1;
    const int bn = tid >> 2, bq = tid & 3;
    const float* Ap = A + (size_t)(m0 + ar) * K + q * 8;
    const float* Bp = B + (size_t)(n0 + bn) * K + bq * 4;

    AccFrag acc[2][2];
#pragma unroll
    for (int i = 0; i < 2; i++)
#pragma unroll
        for (int j = 0; j < 2; j++) wmma::fill_fragment(acc[i][j], 0.f);

    float* As = smem;
    float* Bs = smem + 4352;

#define STAGE_B4(dst, bn, bq, bv)                                           \
    (dst)[((bq) * 4 + 0) * LDB + (bn)] = wmma::__float_to_tf32(bv.x);       \
    (dst)[((bq) * 4 + 1) * LDB + (bn)] = wmma::__float_to_tf32(bv.y);       \
    (dst)[((bq) * 4 + 2) * LDB + (bn)] = wmma::__float_to_tf32(bv.z);       \
    (dst)[((bq) * 4 + 3) * LDB + (bn)] = wmma::__float_to_tf32(bv.w);

    {
        const float4 a0 = *(const float4*)(Ap);
        const float4 a1 = *(const float4*)(Ap + 4);
        const float4 bv = *(const float4*)(Bp);
        STAGE_A8(As, ar, q, a0, a1);
        STAGE_B4(Bs, bn, bq, bv);
    }
    __syncthreads();

    int buf = 0;
    for (int k0 = 16; k0 < K; k0 += 16) {
        const float4 a0 = *(const float4*)(Ap + k0);
        const float4 a1 = *(const float4*)(Ap + k0 + 4);
        const float4 bv = *(const float4*)(Bp + k0);
        mma_chunk(As + buf * 2176, Bs + buf * 1152, acc, wm, wn);
        float* An = As + (buf ^ 1) * 2176;
        float* Bn = Bs + (buf ^ 1) * 1152;
        STAGE_A8(An, ar, q, a0, a1);
        STAGE_B4(Bn, bn, bq, bv);
        __syncthreads();
        buf ^= 1;
    }
    mma_chunk(As + buf * 2176, Bs + buf * 1152, acc, wm, wn);
    __syncthreads();
    store_c_frags(smem, acc, wm, wn);
    __syncthreads();

    const int r = tid >> 1, h = tid & 1;
#pragma unroll
    for (int j = 0; j < 8; j++) {
        const int c = h * 32 + j * 4;
        float4 v = *(float4*)&smem[r * LDC + c];
        float b0 = bias1[n0 + c + 0] + (bias2 ? bias2[n0 + c + 0] : 0.f);
        float b1v = bias1[n0 + c + 1] + (bias2 ? bias2[n0 + c + 1] : 0.f);
        float b2v = bias1[n0 + c + 2] + (bias2 ? bias2[n0 + c + 2] : 0.f);
        float b3v = bias1[n0 + c + 3] + (bias2 ? bias2[n0 + c + 3] : 0.f);
        v.x += b0; v.y += b1v; v.z += b2v; v.w += b3v;
        if (relu) {
            v.x = fmaxf(v.x, 0.f); v.y = fmaxf(v.y, 0.f);
            v.z = fmaxf(v.z, 0.f); v.w = fmaxf(v.w, 0.f);
        }
        *(float4*)&C[(size_t)(m0 + r) * 512 + n0 + c] = v;
    }
}

__global__ __launch_bounds__(256) void fc_gemm_kernel(const float* __restrict__ Wfc,
                                                      const float* __restrict__ bfc) {
    gemm_wmma(g_z3, Wfc, g_hidden, 3136, bfc, nullptr, true);
}
__global__ __launch_bounds__(256) void gates_gemm_kernel(const float* __restrict__ W_ih,
                                                         const float* __restrict__ b_ih,
                                                         const float* __restrict__ b_hh) {
    gemm_wmma(g_hidden, W_ih, g_gates, 512, b_ih, b_hh, false);
}

// ---------------------------------------------------------------------------
// LSTM: one block per batch element, 512 threads (proven coalesced, fp32).
// ---------------------------------------------------------------------------
__device__ __forceinline__ float sigmoidf_(float v) {
    return 1.0f / (1.0f + __expf(-v));
}

__global__ __launch_bounds__(512) void lstm_kernel(const float* __restrict__ done,
                                                   const float* __restrict__ h0,
                                                   const float* __restrict__ c0,
                                                   float* __restrict__ out) {
    __shared__ float hm[HID];
    __shared__ float cs[HID];
    __shared__ float hs[HID];
    __shared__ float part[4 * 512];
    const int b = blockIdx.x;
    const int tid = threadIdx.x;
    const int j4 = tid & 127;
    const int ks = tid >> 7;

    if (tid < HID) {
        hs[tid] = h0[b * HID + tid];
        cs[tid] = c0[b * HID + tid];
    }
    __syncthreads();

    for (int t = 0; t < TSTEPS; t++) {
        const float mask = 1.0f - done[t * BATCH + b];
        if (tid < HID) hm[tid] = hs[tid] * mask;
        __syncthreads();

        float a0 = 0.f, a1 = 0.f, a2 = 0.f, a3 = 0.f;
        const float4* __restrict__ wt = (const float4*)&g_whhT[(ks * 32) * 512] + j4;
        const float* __restrict__ hk = &hm[ks * 32];
#pragma unroll
        for (int kk = 0; kk < 32; kk++) {
            const float4 w = wt[kk * 128];
            const float h = hk[kk];
            a0 += w.x * h; a1 += w.y * h; a2 += w.z * h; a3 += w.w * h;
        }
        float4 pv = {a0, a1, a2, a3};
        *(float4*)&part[ks * 512 + j4 * 4] = pv;
        __syncthreads();

        const float gx = g_gates[(size_t)(t * BATCH + b) * 512 + tid];
        const float gsum = part[tid] + part[512 + tid] + part[1024 + tid] +
                           part[1536 + tid] + gx;
        part[tid] = gsum;
        __syncthreads();

        if (tid < HID) {
            const float gi = part[tid];
            const float gf = part[tid + 128];
            const float gc = part[tid + 256];
            const float go = part[tid + 384];
            float c = cs[tid] * mask;
            c = sigmoidf_(gf) * c + sigmoidf_(gi) * tanhf(gc);
            const float h = sigmoidf_(go) * tanhf(c);
            cs[tid] = c;
            hs[tid] = h;
            g_hs[(size_t)(t * BATCH + b) * HID + tid] = h;
            if (t == TSTEPS - 1) {
                out[28672 + b * HID + tid] = h;
                out[32768 + b * HID + tid] = c;
            }
        }
        __syncthreads();
    }
}

// ---------------------------------------------------------------------------
// Heads: logits (4096x6) and value (4096x1) from g_hs.
// ---------------------------------------------------------------------------
__global__ __launch_bounds__(256) void heads_kernel(const float* __restrict__ Wa,
                                                    const float* __restrict__ ba,
                                                    const float* __restrict__ Wc,
                                                    const float* __restrict__ bc,
                                                    float* __restrict__ out) {
    __shared__ float was[6 * 128];
    __shared__ float wcs[128];
    __shared__ float bas[6];
    __shared__ float bcs;
    const int tid = threadIdx.x;
    for (int i = tid; i < 768; i += 256) was[i] = Wa[i];
    if (tid < 128) wcs[tid] = Wc[tid];
    if (tid < 6) bas[tid] = ba[tid];
    if (tid == 0) bcs = bc[0];
    __syncthreads();

    const int row = blockIdx.x * 256 + tid;
    const float* hp = &g_hs[(size_t)row * 128];
    float acc[6] = {0.f, 0.f, 0.f, 0.f, 0.f, 0.f};
    float accv = 0.f;
    for (int k = 0; k < 128; k += 4) {
        const float4 h4 = *(const float4*)&hp[k];
#pragma unroll
        for (int a = 0; a < 6; a++) {
            const float4 w4 = *(const float4*)&was[a * 128 + k];
            acc[a] += h4.x * w4.x + h4.y * w4.y + h4.z * w4.z + h4.w * w4.w;
        }
        const float4 wc4 = *(const float4*)&wcs[k];
        accv += h4.x * wc4.x + h4.y * wc4.y + h4.z * wc4.z + h4.w * wc4.w;
    }
#pragma unroll
    for (int a = 0; a < 6; a++) out[row * 6 + a] = acc[a] + bas[a];
    out[24576 + row] = accv + bcs;
}

// ---------------------------------------------------------------------------
// Launch
// ---------------------------------------------------------------------------
extern "C" void kernel_launch(void* const* d_in, const int* in_sizes, int n_in,
                              void* d_out, int out_size) {
    const float* x    = (const float*)d_in[0];
    const float* done = (const float*)d_in[1];
    const float* h0   = (const float*)d_in[2];
    const float* c0   = (const float*)d_in[3];
    const float* W1   = (const float*)d_in[4];
    const float* b1   = (const float*)d_in[5];
    const float* W2   = (const float*)d_in[6];
    const float* b2   = (const float*)d_in[7];
    const float* W3   = (const float*)d_in[8];
    const float* b3   = (const float*)d_in[9];
    const float* Wfc  = (const float*)d_in[10];
    const float* bfc  = (const float*)d_in[11];
    const float* W_ih = (const float*)d_in[12];
    const float* W_hh = (const float*)d_in[13];
    const float* b_ih = (const float*)d_in[14];
    const float* b_hh = (const float*)d_in[15];
    const float* Wa   = (const float*)d_in[16];
    const float* ba   = (const float*)d_in[17];
    const float* Wc   = (const float*)d_in[18];
    const float* bc   = (const float*)d_in[19];
    float* out = (float*)d_out;

    whh_transpose_kernel<<<128, 512>>>(W_hh);
    w1t_kernel<<<8, 256>>>(W1);
    w2t_kernel<<<128, 256>>>(W2);
    w3t_kernel<<<144, 256>>>(W3);
    conv1_gemm_kernel<<<12800, 256>>>(x, b1);
    conv2_wmma_kernel<<<2592, 256>>>(b2);
    conv3_wmma_kernel<<<1568, 256>>>(b3);
    fc_gemm_kernel<<<dim3(8, 32), 256>>>(Wfc, bfc);
    gates_gemm_kernel<<<dim3(8, 32), 256>>>(W_ih, b_ih, b_hh);
    lstm_kernel<<<BATCH, 512>>>(done, h0, c0, out);
    heads_kernel<<<16, 256>>>(Wa, ba, Wc, bc, out);
}

// round 11
// speedup vs baseline: 3.6698x; 1.0104x over previous
#include <cuda_runtime.h>
#include <mma.h>
#include <cstdint>

using namespace nvcuda;

#define NIMG   4096
#define TSTEPS 128
#define BATCH  32
#define HID    128

// Scratch (device globals; no allocation allowed)
__device__ float g_z1[(size_t)NIMG * 4 * 400 * 8];    // conv1 out [n][c=ic/8][pix400][ic%8]
__device__ float g_z2[(size_t)NIMG * 4 * 81 * 16];    // conv2 out [n][cc=oc/16][pix81][oc%16]
__device__ float g_z3[(size_t)NIMG * 3136];           // conv3 out, NCHW flatten
__device__ float g_hidden[(size_t)NIMG * 512];        // FC out
__device__ float g_gates[(size_t)NIMG * 512];         // x-proj of gates (+both biases)
__device__ float g_hs[(size_t)NIMG * HID];            // per-step hidden outputs
__device__ float g_whhT[HID * 512];                   // W_hh transposed
__device__ float g_w1t[64 * 32];                      // W1/255 in [k][oc] (tf32-rounded)
__device__ float g_w2t[512 * 64];                     // W2 in [k][oc]  (tf32-rounded)
__device__ float g_w3t[576 * 64];                     // W3 in [k][oc]  (tf32-rounded)

// ---------------------------------------------------------------------------
// Weight re-layout preps (conv weights stored pre-rounded to tf32)
// ---------------------------------------------------------------------------
__global__ __launch_bounds__(256) void w1t_kernel(const float* __restrict__ W1) {
    const int id = blockIdx.x * 256 + threadIdx.x;   // 0..2047
    const int k = id >> 5, oc = id & 31;
    g_w1t[k * 32 + oc] = wmma::__float_to_tf32(W1[oc * 64 + k] * (1.0f / 255.0f));
}
__global__ __launch_bounds__(256) void w2t_kernel(const float* __restrict__ W2) {
    const int id = blockIdx.x * 256 + threadIdx.x;   // 0..32767
    const int k = id >> 6, oc = id & 63;
    const int c = k >> 7, k16 = (k & 127) >> 3, icl = k & 7;
    g_w2t[k * 64 + oc] = wmma::__float_to_tf32(W2[oc * 512 + (c * 8 + icl) * 16 + k16]);
}
__global__ __launch_bounds__(256) void w3t_kernel(const float* __restrict__ W3) {
    const int id = blockIdx.x * 256 + threadIdx.x;   // 0..36863
    const int k = id >> 6, oc = id & 63;
    const int icc = k / 144, rem = k % 144, k9 = rem >> 4, icl = rem & 15;
    g_w3t[k * 64 + oc] = wmma::__float_to_tf32(W3[oc * 576 + (icc * 16 + icl) * 9 + k9]);
}
__global__ __launch_bounds__(512) void whh_transpose_kernel(const float* __restrict__ W_hh) {
    const int id = blockIdx.x * 512 + threadIdx.x;   // 0..65535
    const int k = id >> 9, j = id & 511;
    g_whhT[k * 512 + j] = W_hh[j * 128 + k];
}

// ---------------------------------------------------------------------------
// TF32 WMMA common pieces. 256 threads, BK=16, double-buffered smem.
// ---------------------------------------------------------------------------
#define LDA 136
#define LDB 72
#define LDC 72

typedef wmma::fragment<wmma::accumulator, 16, 16, 8, float> AccFrag;

__device__ __forceinline__ void mma_chunk(const float* __restrict__ As,
                                          const float* __restrict__ Bs,
                                          AccFrag (&acc)[2][2], int wm, int wn) {
#pragma unroll
    for (int ks = 0; ks < 16; ks += 8) {
        wmma::fragment<wmma::matrix_a, 16, 16, 8, wmma::precision::tf32, wmma::col_major> a[2];
        wmma::fragment<wmma::matrix_b, 16, 16, 8, wmma::precision::tf32, wmma::row_major> b[2];
#pragma unroll
        for (int i = 0; i < 2; i++)
            wmma::load_matrix_sync(a[i], As + ks * LDA + wm * 32 + i * 16, LDA);
#pragma unroll
        for (int j = 0; j < 2; j++)
            wmma::load_matrix_sync(b[j], Bs + ks * LDB + wn * 32 + j * 16, LDB);
#pragma unroll
        for (int i = 0; i < 2; i++)
#pragma unroll
            for (int j = 0; j < 2; j++)
                wmma::mma_sync(acc[i][j], a[i], b[j], acc[i][j]);
    }
}

// stage 8 consecutive-k A values (tf32-rounded at store)
#define STAGE_A8(dst, ar, q, v0, v1)                                  \
    {                                                                 \
        const int _kb = (q) * 8;                                      \
        (dst)[(_kb + 0) * LDA + (ar)] = wmma::__float_to_tf32(v0.x);  \
        (dst)[(_kb + 1) * LDA + (ar)] = wmma::__float_to_tf32(v0.y);  \
        (dst)[(_kb + 2) * LDA + (ar)] = wmma::__float_to_tf32(v0.z);  \
        (dst)[(_kb + 3) * LDA + (ar)] = wmma::__float_to_tf32(v0.w);  \
        (dst)[(_kb + 4) * LDA + (ar)] = wmma::__float_to_tf32(v1.x);  \
        (dst)[(_kb + 5) * LDA + (ar)] = wmma::__float_to_tf32(v1.y);  \
        (dst)[(_kb + 6) * LDA + (ar)] = wmma::__float_to_tf32(v1.z);  \
        (dst)[(_kb + 7) * LDA + (ar)] = wmma::__float_to_tf32(v1.w);  \
    }

__device__ __forceinline__ void store_c_frags(float* smem, AccFrag (&acc)[2][2],
                                              int wm, int wn) {
#pragma unroll
    for (int i = 0; i < 2; i++)
#pragma unroll
        for (int j = 0; j < 2; j++)
            wmma::store_matrix_sync(&smem[(wm * 32 + i * 16) * LDC + wn * 32 + j * 16],
                                    acc[i][j], LDC, wmma::mem_row_major);
}

// ---------------------------------------------------------------------------
// conv1 TF32 WMMA: M=1638400 rows (n,p), N=32 oc, K=64. 1/255 in g_w1t.
// Warp grid 4x2, warp tile 32x16 (a[2], b[1]). Bs is 16x32 (LDB1=36).
// ---------------------------------------------------------------------------
#define LDB1 36
#define LDC1 36

__global__ __launch_bounds__(256) void conv1_wmma_kernel(const float* __restrict__ x,
                                                         const float* __restrict__ b1) {
    __shared__ float smem[5504];   // As 2x2176 | Bs 2x576 ; C stage 128x36 reuses front
    const int tid = threadIdx.x;
    const int wid = tid >> 5, wm = wid >> 1, wn = wid & 1;
    const int m0 = blockIdx.x * 128;
    const int ar = tid >> 1, q = tid & 1;
    const int m = m0 + ar;
    const int an = m / 400, ap = m % 400;
    const int iy = (ap / 20) * 4, ix = (ap % 20) * 4;
    const float* xrow = x + (size_t)an * 7056 + ix;
    const int kb = tid >> 3, ob = (tid & 7) << 2;   // B loader: threads 0..127

    AccFrag acc1[2];
#pragma unroll
    for (int i = 0; i < 2; i++) wmma::fill_fragment(acc1[i], 0.f);

    float* As = smem;
    float* Bs = smem + 4352;

#define C1_LOADA(k0, v0, v1)                                   \
    {                                                          \
        const int ky = ((k0) >> 3) + q;                        \
        const float* xp = xrow + (iy + ky) * 84;               \
        v0 = *(const float4*)(xp);                             \
        v1 = *(const float4*)(xp + 4);                         \
    }

    {
        float4 a0, a1;
        C1_LOADA(0, a0, a1);
        float4 bv;
        if (tid < 128) bv = *(const float4*)&g_w1t[kb * 32 + ob];
        STAGE_A8(As, ar, q, a0, a1);
        if (tid < 128) *(float4*)&Bs[kb * LDB1 + ob] = bv;
    }
    __syncthreads();

    int buf = 0;
    for (int k0 = 16; k0 < 64; k0 += 16) {
        float4 a0, a1;
        C1_LOADA(k0, a0, a1);
        float4 bv;
        if (tid < 128) bv = *(const float4*)&g_w1t[(k0 + kb) * 32 + ob];
        // mma on current buffer
#pragma unroll
        for (int ks = 0; ks < 16; ks += 8) {
            wmma::fragment<wmma::matrix_a, 16, 16, 8, wmma::precision::tf32, wmma::col_major> a[2];
            wmma::fragment<wmma::matrix_b, 16, 16, 8, wmma::precision::tf32, wmma::row_major> b;
#pragma unroll
            for (int i = 0; i < 2; i++)
                wmma::load_matrix_sync(a[i], As + buf * 2176 + ks * LDA + wm * 32 + i * 16, LDA);
            wmma::load_matrix_sync(b, Bs + buf * 576 + ks * LDB1 + wn * 16, LDB1);
#pragma unroll
            for (int i = 0; i < 2; i++)
                wmma::mma_sync(acc1[i], a[i], b, acc1[i]);
        }
        float* An = As + (buf ^ 1) * 2176;
        float* Bn = Bs + (buf ^ 1) * 576;
        STAGE_A8(An, ar, q, a0, a1);
        if (tid < 128) *(float4*)&Bn[kb * LDB1 + ob] = bv;
        __syncthreads();
        buf ^= 1;
    }
#pragma unroll
    for (int ks = 0; ks < 16; ks += 8) {
        wmma::fragment<wmma::matrix_a, 16, 16, 8, wmma::precision::tf32, wmma::col_major> a[2];
        wmma::fragment<wmma::matrix_b, 16, 16, 8, wmma::precision::tf32, wmma::row_major> b;
#pragma unroll
        for (int i = 0; i < 2; i++)
            wmma::load_matrix_sync(a[i], As + buf * 2176 + ks * LDA + wm * 32 + i * 16, LDA);
        wmma::load_matrix_sync(b, Bs + buf * 576 + ks * LDB1 + wn * 16, LDB1);
#pragma unroll
        for (int i = 0; i < 2; i++)
            wmma::mma_sync(acc1[i], a[i], b, acc1[i]);
    }
    __syncthreads();
#pragma unroll
    for (int i = 0; i < 2; i++)
        wmma::store_matrix_sync(&smem[(wm * 32 + i * 16) * LDC1 + wn * 16], acc1[i],
                                LDC1, wmma::mem_row_major);
    __syncthreads();

    const int r = tid >> 1, h = tid & 1;
    const int rn = (m0 + r) / 400, rp = (m0 + r) % 400;
#pragma unroll
    for (int j = 0; j < 2; j++) {
        const int oc = h * 16 + j * 8;
#pragma unroll
        for (int s = 0; s < 2; s++) {
            const int oc4 = oc + s * 4;
            float4 v = *(float4*)&smem[r * LDC1 + oc4];
            const float4 bb = *(const float4*)&b1[oc4];
            v.x = fmaxf(v.x + bb.x, 0.f);
            v.y = fmaxf(v.y + bb.y, 0.f);
            v.z = fmaxf(v.z + bb.z, 0.f);
            v.w = fmaxf(v.w + bb.w, 0.f);
            const int g = oc4 >> 3, l = oc4 & 7;
            *(float4*)&g_z1[((size_t)rn * 4 + g) * 3200 + rp * 8 + l] = v;
        }
    }
}

// ---------------------------------------------------------------------------
// conv2 TF32: M=331776 (=(n,p)), K=512, N=64.  (weights pre-rounded in g_w2t)
// ---------------------------------------------------------------------------
__global__ __launch_bounds__(256) void conv2_wmma_kernel(const float* __restrict__ b2) {
    __shared__ float smem[9216];
    const int tid = threadIdx.x;
    const int wid = tid >> 5, wm = wid >> 1, wn = wid & 1;
    const int m0 = blockIdx.x * 128;
    const int ar = tid >> 1, q = tid & 1;
    const int m = m0 + ar;
    const int an = m / 81, ap = m % 81;
    const int aiy = (ap / 9) * 2, aix = (ap % 9) * 2;
    const int kb = tid >> 4, ob = (tid & 15) << 2;

    AccFrag acc[2][2];
#pragma unroll
    for (int i = 0; i < 2; i++)
#pragma unroll
        for (int j = 0; j < 2; j++) wmma::fill_fragment(acc[i][j], 0.f);

    float* As = smem;
    float* Bs = smem + 4352;

#define C2_LOADA(k0, v0, v1)                                                     \
    {                                                                            \
        const int g = ((k0) >> 3) + q;                                           \
        const int c = g >> 4, k16 = g & 15;                                      \
        const int ky = k16 >> 2, kx = k16 & 3;                                   \
        const float* p = &g_z1[(((size_t)an * 4 + c) * 400 +                     \
                                (aiy + ky) * 20 + aix + kx) * 8];                \
        v0 = *(const float4*)p; v1 = *(const float4*)(p + 4);                    \
    }

    {
        float4 a0, a1;
        C2_LOADA(0, a0, a1);
        const float4 bv = *(const float4*)&g_w2t[(size_t)kb * 64 + ob];
        STAGE_A8(As, ar, q, a0, a1);
        *(float4*)&Bs[kb * LDB + ob] = bv;
    }
    __syncthreads();

    int buf = 0;
    for (int k0 = 16; k0 < 512; k0 += 16) {
        float4 a0, a1;
        C2_LOADA(k0, a0, a1);
        const float4 bv = *(const float4*)&g_w2t[(size_t)(k0 + kb) * 64 + ob];
        mma_chunk(As + buf * 2176, Bs + buf * 1152, acc, wm, wn);
        float* An = As + (buf ^ 1) * 2176;
        float* Bn = Bs + (buf ^ 1) * 1152;
        STAGE_A8(An, ar, q, a0, a1);
        *(float4*)&Bn[kb * LDB + ob] = bv;
        __syncthreads();
        buf ^= 1;
    }
    mma_chunk(As + buf * 2176, Bs + buf * 1152, acc, wm, wn);
    __syncthreads();
    store_c_frags(smem, acc, wm, wn);
    __syncthreads();

    const int r = tid >> 1, h = tid & 1;
    const int rn = (m0 + r) / 81, rp = (m0 + r) % 81;
#pragma unroll
    for (int j = 0; j < 8; j++) {
        const int oc = h * 32 + j * 4;
        float4 v = *(float4*)&smem[r * LDC + oc];
        const float4 bb = *(const float4*)&b2[oc];
        v.x = fmaxf(v.x + bb.x, 0.f);
        v.y = fmaxf(v.y + bb.y, 0.f);
        v.z = fmaxf(v.z + bb.z, 0.f);
        v.w = fmaxf(v.w + bb.w, 0.f);
        *(float4*)&g_z2[(((size_t)rn * 4 + (oc >> 4)) * 81 + rp) * 16 + (oc & 15)] = v;
    }
}

// ---------------------------------------------------------------------------
// conv3 TF32: M=200704 (=(n,p)), K=576, N=64.  (weights pre-rounded in g_w3t)
// ---------------------------------------------------------------------------
__global__ __launch_bounds__(256) void conv3_wmma_kernel(const float* __restrict__ b3) {
    __shared__ float smem[9216];
    const int tid = threadIdx.x;
    const int wid = tid >> 5, wm = wid >> 1, wn = wid & 1;
    const int m0 = blockIdx.x * 128;
    const int ar = tid >> 1, q = tid & 1;
    const int m = m0 + ar;
    const int an = m / 49, ap = m % 49;
    const int aoy = ap / 7, aox = ap % 7;
    const int kb = tid >> 4, ob = (tid & 15) << 2;

    AccFrag acc[2][2];
#pragma unroll
    for (int i = 0; i < 2; i++)
#pragma unroll
        for (int j = 0; j < 2; j++) wmma::fill_fragment(acc[i][j], 0.f);

    float* As = smem;
    float* Bs = smem + 4352;

#define C3_LOADA(k0, v0, v1)                                                     \
    {                                                                            \
        const int g = (k0) >> 4;                                                 \
        const int icc = g / 9, k9 = g % 9;                                       \
        const int ky = k9 / 3, kx = k9 % 3;                                      \
        const float* p = &g_z2[(((size_t)an * 4 + icc) * 81 +                    \
                                (aoy + ky) * 9 + aox + kx) * 16 + q * 8];        \
        v0 = *(const float4*)p; v1 = *(const float4*)(p + 4);                    \
    }

    {
        float4 a0, a1;
        C3_LOADA(0, a0, a1);
        const float4 bv = *(const float4*)&g_w3t[(size_t)kb * 64 + ob];
        STAGE_A8(As, ar, q, a0, a1);
        *(float4*)&Bs[kb * LDB + ob] = bv;
    }
    __syncthreads();

    int buf = 0;
    for (int k0 = 16; k0 < 576; k0 += 16) {
        float4 a0, a1;
        C3_LOADA(k0, a0, a1);
        const float4 bv = *(const float4*)&g_w3t[(size_t)(k0 + kb) * 64 + ob];
        mma_chunk(As + buf * 2176, Bs + buf * 1152, acc, wm, wn);
        float* An = As + (buf ^ 1) * 2176;
        float* Bn = Bs + (buf ^ 1) * 1152;
        STAGE_A8(An, ar, q, a0, a1);
        *(float4*)&Bn[kb * LDB + ob] = bv;
        __syncthreads();
        buf ^= 1;
    }
    mma_chunk(As + buf * 2176, Bs + buf * 1152, acc, wm, wn);
    __syncthreads();
    store_c_frags(smem, acc, wm, wn);
    __syncthreads();

    const int r = tid >> 1, h = tid & 1;
    const int rn = (m0 + r) / 49, rp = (m0 + r) % 49;
#pragma unroll
    for (int j = 0; j < 8; j++) {
        const int oc = h * 32 + j * 4;
        const float4 v = *(float4*)&smem[r * LDC + oc];
        const float4 bb = *(const float4*)&b3[oc];
        float* zp = &g_z3[(size_t)rn * 3136 + oc * 49 + rp];
        zp[0]   = fmaxf(v.x + bb.x, 0.f);
        zp[49]  = fmaxf(v.y + bb.y, 0.f);
        zp[98]  = fmaxf(v.z + bb.z, 0.f);
        zp[147] = fmaxf(v.w + bb.w, 0.f);
    }
}

// ---------------------------------------------------------------------------
// Dense TF32 GEMM (fc / gates): tf32-rounded at staging for both A and B.
// ---------------------------------------------------------------------------
__device__ __forceinline__ void gemm_wmma(const float* __restrict__ A,
                                          const float* __restrict__ B,
                                          float* __restrict__ C, int K,
                                          const float* __restrict__ bias1,
                                          const float* __restrict__ bias2,
                                          bool relu) {
    __shared__ float smem[9216];
    const int tid = threadIdx.x;
    const int wid = tid >> 5, wm = wid >> 1, wn = wid & 1;
    const int m0 = blockIdx.y * 128, n0 = blockIdx.x * 64;
    const int ar = tid >> 1, q = tid & 1;
    const int bn = tid >> 2, bq = tid & 3;
    const float* Ap = A + (size_t)(m0 + ar) * K + q * 8;
    const float* Bp = B + (size_t)(n0 + bn) * K + bq * 4;

    AccFrag acc[2][2];
#pragma unroll
    for (int i = 0; i < 2; i++)
#pragma unroll
        for (int j = 0; j < 2; j++) wmma::fill_fragment(acc[i][j], 0.f);

    float* As = smem;
    float* Bs = smem + 4352;

#define STAGE_B4(dst, bn, bq, bv)                                           \
    (dst)[((bq) * 4 + 0) * LDB + (bn)] = wmma::__float_to_tf32(bv.x);       \
    (dst)[((bq) * 4 + 1) * LDB + (bn)] = wmma::__float_to_tf32(bv.y);       \
    (dst)[((bq) * 4 + 2) * LDB + (bn)] = wmma::__float_to_tf32(bv.z);       \
    (dst)[((bq) * 4 + 3) * LDB + (bn)] = wmma::__float_to_tf32(bv.w);

    {
        const float4 a0 = *(const float4*)(Ap);
        const float4 a1 = *(const float4*)(Ap + 4);
        const float4 bv = *(const float4*)(Bp);
        STAGE_A8(As, ar, q, a0, a1);
        STAGE_B4(Bs, bn, bq, bv);
    }
    __syncthreads();

    int buf = 0;
    for (int k0 = 16; k0 < K; k0 += 16) {
        const float4 a0 = *(const float4*)(Ap + k0);
        const float4 a1 = *(const float4*)(Ap + k0 + 4);
        const float4 bv = *(const float4*)(Bp + k0);
        mma_chunk(As + buf * 2176, Bs + buf * 1152, acc, wm, wn);
        float* An = As + (buf ^ 1) * 2176;
        float* Bn = Bs + (buf ^ 1) * 1152;
        STAGE_A8(An, ar, q, a0, a1);
        STAGE_B4(Bn, bn, bq, bv);
        __syncthreads();
        buf ^= 1;
    }
    mma_chunk(As + buf * 2176, Bs + buf * 1152, acc, wm, wn);
    __syncthreads();
    store_c_frags(smem, acc, wm, wn);
    __syncthreads();

    const int r = tid >> 1, h = tid & 1;
#pragma unroll
    for (int j = 0; j < 8; j++) {
        const int c = h * 32 + j * 4;
        float4 v = *(float4*)&smem[r * LDC + c];
        float b0 = bias1[n0 + c + 0] + (bias2 ? bias2[n0 + c + 0] : 0.f);
        float b1v = bias1[n0 + c + 1] + (bias2 ? bias2[n0 + c + 1] : 0.f);
        float b2v = bias1[n0 + c + 2] + (bias2 ? bias2[n0 + c + 2] : 0.f);
        float b3v = bias1[n0 + c + 3] + (bias2 ? bias2[n0 + c + 3] : 0.f);
        v.x += b0; v.y += b1v; v.z += b2v; v.w += b3v;
        if (relu) {
            v.x = fmaxf(v.x, 0.f); v.y = fmaxf(v.y, 0.f);
            v.z = fmaxf(v.z, 0.f); v.w = fmaxf(v.w, 0.f);
        }
        *(float4*)&C[(size_t)(m0 + r) * 512 + n0 + c] = v;
    }
}

__global__ __launch_bounds__(256) void fc_gemm_kernel(const float* __restrict__ Wfc,
                                                      const float* __restrict__ bfc) {
    gemm_wmma(g_z3, Wfc, g_hidden, 3136, bfc, nullptr, true);
}
__global__ __launch_bounds__(256) void gates_gemm_kernel(const float* __restrict__ W_ih,
                                                         const float* __restrict__ b_ih,
                                                         const float* __restrict__ b_hh) {
    gemm_wmma(g_hidden, W_ih, g_gates, 512, b_ih, b_hh, false);
}

// ---------------------------------------------------------------------------
// LSTM: one block per batch element, 512 threads (proven coalesced, fp32).
// ---------------------------------------------------------------------------
__device__ __forceinline__ float sigmoidf_(float v) {
    return 1.0f / (1.0f + __expf(-v));
}

__global__ __launch_bounds__(512) void lstm_kernel(const float* __restrict__ done,
                                                   const float* __restrict__ h0,
                                                   const float* __restrict__ c0,
                                                   float* __restrict__ out) {
    __shared__ float hm[HID];
    __shared__ float cs[HID];
    __shared__ float hs[HID];
    __shared__ float part[4 * 512];
    const int b = blockIdx.x;
    const int tid = threadIdx.x;
    const int j4 = tid & 127;
    const int ks = tid >> 7;

    if (tid < HID) {
        hs[tid] = h0[b * HID + tid];
        cs[tid] = c0[b * HID + tid];
    }
    __syncthreads();

    for (int t = 0; t < TSTEPS; t++) {
        const float mask = 1.0f - done[t * BATCH + b];
        if (tid < HID) hm[tid] = hs[tid] * mask;
        __syncthreads();

        float a0 = 0.f, a1 = 0.f, a2 = 0.f, a3 = 0.f;
        const float4* __restrict__ wt = (const float4*)&g_whhT[(ks * 32) * 512] + j4;
        const float* __restrict__ hk = &hm[ks * 32];
#pragma unroll
        for (int kk = 0; kk < 32; kk++) {
            const float4 w = wt[kk * 128];
            const float h = hk[kk];
            a0 += w.x * h; a1 += w.y * h; a2 += w.z * h; a3 += w.w * h;
        }
        float4 pv = {a0, a1, a2, a3};
        *(float4*)&part[ks * 512 + j4 * 4] = pv;
        __syncthreads();

        const float gx = g_gates[(size_t)(t * BATCH + b) * 512 + tid];
        const float gsum = part[tid] + part[512 + tid] + part[1024 + tid] +
                           part[1536 + tid] + gx;
        part[tid] = gsum;
        __syncthreads();

        if (tid < HID) {
            const float gi = part[tid];
            const float gf = part[tid + 128];
            const float gc = part[tid + 256];
            const float go = part[tid + 384];
            float c = cs[tid] * mask;
            c = sigmoidf_(gf) * c + sigmoidf_(gi) * tanhf(gc);
            const float h = sigmoidf_(go) * tanhf(c);
            cs[tid] = c;
            hs[tid] = h;
            g_hs[(size_t)(t * BATCH + b) * HID + tid] = h;
            if (t == TSTEPS - 1) {
                out[28672 + b * HID + tid] = h;
                out[32768 + b * HID + tid] = c;
            }
        }
        __syncthreads();
    }
}

// ---------------------------------------------------------------------------
// Heads: logits (4096x6) and value (4096x1) from g_hs.
// ---------------------------------------------------------------------------
__global__ __launch_bounds__(256) void heads_kernel(const float* __restrict__ Wa,
                                                    const float* __restrict__ ba,
                                                    const float* __restrict__ Wc,
                                                    const float* __restrict__ bc,
                                                    float* __restrict__ out) {
    __shared__ float was[6 * 128];
    __shared__ float wcs[128];
    __shared__ float bas[6];
    __shared__ float bcs;
    const int tid = threadIdx.x;
    for (int i = tid; i < 768; i += 256) was[i] = Wa[i];
    if (tid < 128) wcs[tid] = Wc[tid];
    if (tid < 6) bas[tid] = ba[tid];
    if (tid == 0) bcs = bc[0];
    __syncthreads();

    const int row = blockIdx.x * 256 + tid;
    const float* hp = &g_hs[(size_t)row * 128];
    float acc[6] = {0.f, 0.f, 0.f, 0.f, 0.f, 0.f};
    float accv = 0.f;
    for (int k = 0; k < 128; k += 4) {
        const float4 h4 = *(const float4*)&hp[k];
#pragma unroll
        for (int a = 0; a < 6; a++) {
            const float4 w4 = *(const float4*)&was[a * 128 + k];
            acc[a] += h4.x * w4.x + h4.y * w4.y + h4.z * w4.z + h4.w * w4.w;
        }
        const float4 wc4 = *(const float4*)&wcs[k];
        accv += h4.x * wc4.x + h4.y * wc4.y + h4.z * wc4.z + h4.w * wc4.w;
    }
#pragma unroll
    for (int a = 0; a < 6; a++) out[row * 6 + a] = acc[a] + bas[a];
    out[24576 + row] = accv + bcs;
}

// ---------------------------------------------------------------------------
// Launch
// ---------------------------------------------------------------------------
extern "C" void kernel_launch(void* const* d_in, const int* in_sizes, int n_in,
                              void* d_out, int out_size) {
    const float* x    = (const float*)d_in[0];
    const float* done = (const float*)d_in[1];
    const float* h0   = (const float*)d_in[2];
    const float* c0   = (const float*)d_in[3];
    const float* W1   = (const float*)d_in[4];
    const float* b1   = (const float*)d_in[5];
    const float* W2   = (const float*)d_in[6];
    const float* b2   = (const float*)d_in[7];
    const float* W3   = (const float*)d_in[8];
    const float* b3   = (const float*)d_in[9];
    const float* Wfc  = (const float*)d_in[10];
    const float* bfc  = (const float*)d_in[11];
    const float* W_ih = (const float*)d_in[12];
    const float* W_hh = (const float*)d_in[13];
    const float* b_ih = (const float*)d_in[14];
    const float* b_hh = (const float*)d_in[15];
    const float* Wa   = (const float*)d_in[16];
    const float* ba   = (const float*)d_in[17];
    const float* Wc   = (const float*)d_in[18];
    const float* bc   = (const float*)d_in[19];
    float* out = (float*)d_out;

    whh_transpose_kernel<<<128, 512>>>(W_hh);
    w1t_kernel<<<8, 256>>>(W1);
    w2t_kernel<<<128, 256>>>(W2);
    w3t_kernel<<<144, 256>>>(W3);
    conv1_wmma_kernel<<<12800, 256>>>(x, b1);
    conv2_wmma_kernel<<<2592, 256>>>(b2);
    conv3_wmma_kernel<<<1568, 256>>>(b3);
    fc_gemm_kernel<<<dim3(8, 32), 256>>>(Wfc, bfc);
    gates_gemm_kernel<<<dim3(8, 32), 256>>>(W_ih, b_ih, b_hh);
    lstm_kernel<<<BATCH, 512>>>(done, h0, c0, out);
    heads_kernel<<<16, 256>>>(Wa, ba, Wc, bc, out);
}